// round 4
// baseline (speedup 1.0000x reference)
#include <cuda_runtime.h>
#include <math.h>

// ---------------- problem geometry ----------------
#define LTOT 28928          // tokens per batch across seqs 0..3
#define BTOK 231424         // 8 * LTOT
#define TOTC 452            // chunks (T=64) per batch: 341+85+21+5
#define NB   8

// ---------------- static device scratch ----------------
__device__ float g_x8[8][BTOK];     // gathered dm=8 input tokens (channel-major)
__device__ float g_xz[32][BTOK];    // in-proj output: xi (0..15), z (16..31)
__device__ float g_rec[64][BTOK];   // per-token record: delta(0..15) xc(16..31) B(32..47) C(48..63)
__device__ float g_P[NB*TOTC*256];  // per-chunk product of a
__device__ float g_S[NB*TOTC*256];  // per-chunk local scan end (h_start=0)
__device__ float g_H[NB*TOTC*256];  // h_start per chunk

__constant__ int c_plen[5]  = {16384,4096,1024,256,64};      // spatial size per tensor (= ch stride)
__constant__ int c_bs[5]    = {131072,65536,24576,8192,3072};// batch stride per tensor
__constant__ int c_obase[5] = {0,1048576,1572864,1769472,1835008};
__constant__ int c_O[4]     = {0,21824,27264,28608};         // seq offsets within a batch
__constant__ int c_CB[4]    = {0,341,426,447};               // chunk base per seq
__constant__ int c_NC[4]    = {341,85,21,5};                 // chunks per seq

__device__ __forceinline__ float siluf(float x){ return x * (1.0f/(1.0f+__expf(-x))); }
__device__ __forceinline__ float softplusf(float x){ return (x>20.0f)? x : log1pf(__expf(x)); }

// ---------------- K1: gather + in-projection ----------------
__global__ void k1_gather(const float* __restrict__ t1, const float* __restrict__ t2,
                          const float* __restrict__ t3, const float* __restrict__ t4,
                          const float* __restrict__ t5, const float* __restrict__ in_w){
  __shared__ float s_w[256]; // (32,8)
  int tid = threadIdx.x;
  if (tid < 256) s_w[tid] = in_w[tid];
  __syncthreads();
  int tg = blockIdx.x*256 + tid;           // < BTOK exactly (904 blocks)
  int b = tg / LTOT, r = tg % LTOT;
  int s = (r>=21824)+(r>=27264)+(r>=28608);
  int p = r - c_O[s];
  int i = s, pp = p;
  while (pp >= c_plen[i]) { pp -= c_plen[i]; ++i; }
  const float* tp = (i==0)?t1:(i==1)?t2:(i==2)?t3:(i==3)?t4:t5;
  int base = b*c_bs[i] + (8*s)*c_plen[i] + pp;
  float x[8];
  #pragma unroll
  for (int c=0;c<8;c++){ x[c] = tp[base + c*c_plen[i]]; g_x8[c][tg] = x[c]; }
  #pragma unroll
  for (int j=0;j<32;j++){
    float v = 0.f;
    #pragma unroll
    for (int c=0;c<8;c++) v += x[c]*s_w[j*8+c];
    g_xz[j][tg] = v;
  }
}

// ---------------- K2: conv + silu + x-proj + softplus -> records ----------------
__global__ void k2_pre(const float* __restrict__ conv_w, const float* __restrict__ conv_b,
                       const float* __restrict__ xproj_w, const float* __restrict__ dt_w,
                       const float* __restrict__ dt_b){
  __shared__ float s_xp[33*16];
  __shared__ float s_cw[64], s_cb[16], s_dtw[16], s_dtb[16];
  int tid = threadIdx.x;
  for (int i=tid;i<33*16;i+=256) s_xp[i]=xproj_w[i];
  if (tid<64) s_cw[tid]=conv_w[tid];
  if (tid<16){ s_cb[tid]=conv_b[tid]; s_dtw[tid]=dt_w[tid]; s_dtb[tid]=dt_b[tid]; }
  __syncthreads();
  int tg = blockIdx.x*256+tid;
  int r = tg % LTOT;
  int s = (r>=21824)+(r>=27264)+(r>=28608);
  int p = r - c_O[s];
  float xc[16];
  #pragma unroll
  for (int d=0;d<16;d++){
    float acc = s_cb[d];
    #pragma unroll
    for (int k=0;k<4;k++){
      int back = 3-k;
      float v = (p>=back)? g_xz[d][tg-back] : 0.0f;
      acc += s_cw[d*4+k]*v;
    }
    xc[d] = siluf(acc);
    g_rec[16+d][tg] = xc[d];
  }
  float dt = 0.f;
  #pragma unroll
  for (int d=0;d<16;d++) dt += xc[d]*s_xp[d];   // xproj row 0
  #pragma unroll
  for (int d=0;d<16;d++) g_rec[d][tg] = softplusf(dt*s_dtw[d]+s_dtb[d]);
  #pragma unroll
  for (int j=0;j<16;j++){
    float bv=0.f, cv=0.f;
    #pragma unroll
    for (int d=0;d<16;d++){ bv += xc[d]*s_xp[(1+j)*16+d]; cv += xc[d]*s_xp[(17+j)*16+d]; }
    g_rec[32+j][tg]=bv; g_rec[48+j][tg]=cv;
  }
}

// ---------------- K3: phase A — per-chunk (P, S) ----------------
__global__ void k3_scanA(const float* __restrict__ Alog){
  int blk = blockIdx.x;
  int b = blk / TOTC, cg = blk % TOTC;
  int s = (cg>=341)+(cg>=426)+(cg>=447);
  int tb = b*LTOT + c_O[s] + (cg - c_CB[s])*64;
  __shared__ float sh[48][65];
  int tid = threadIdx.x;
  for (int i=tid;i<48*16;i+=256){
    int c=i>>4, q=i&15;
    float4 v = *reinterpret_cast<const float4*>(&g_rec[c][tb] + q*4);
    sh[c][q*4+0]=v.x; sh[c][q*4+1]=v.y; sh[c][q*4+2]=v.z; sh[c][q*4+3]=v.w;
  }
  int d = tid>>4, n = tid&15;
  float ac = -__expf(Alog[d*16+n])*1.4426950408889634f;
  __syncthreads();
  float h=0.f, P=1.f;
  #pragma unroll 8
  for (int t=0;t<64;t++){
    float dl = sh[d][t];
    float a = exp2f(dl*ac);
    h = a*h + dl*sh[16+d][t]*sh[32+n][t];
    P *= a;
  }
  int idx = (b*TOTC+cg)*256+tid;
  g_P[idx]=P; g_S[idx]=h;
}

// ---------------- K4: chunk-prefix scan -> h_start per chunk ----------------
__global__ void k4_chunk(){
  int b = blockIdx.x >> 2, s = blockIdx.x & 3;
  int tid = threadIdx.x;
  float H = 0.f;
  int base = (b*TOTC + c_CB[s])*256 + tid;
  int nc = c_NC[s];
  for (int c=0;c<nc;c++){
    int idx = base + c*256;
    g_H[idx] = H;
    H = g_P[idx]*H + g_S[idx];
  }
}

// ---------------- K5: phase C — scan replay + full epilogue + scatter ----------------
__global__ void k5_scanC(const float* __restrict__ Alog, const float* __restrict__ out_w,
                         const float* __restrict__ Dv, const float* __restrict__ ng,
                         const float* __restrict__ nbv, const float* __restrict__ pw,
                         const float* __restrict__ pb, const float* __restrict__ skipp,
                         float* __restrict__ out){
  int blk = blockIdx.x;
  int b = blk / TOTC, cg = blk % TOTC;
  int s = (cg>=341)+(cg>=426)+(cg>=447);
  int cis = cg - c_CB[s];
  int tb = b*LTOT + c_O[s] + cis*64;
  __shared__ float sh[64][65];
  __shared__ float ysh[64][16];
  __shared__ float s_ow[128], s_pw[64], s_pb[8], s_g[8], s_nb[8], s_D[16];
  __shared__ float s_skip;
  int tid = threadIdx.x;
  for (int i=tid;i<64*16;i+=256){
    int c=i>>4, q=i&15;
    float4 v = *reinterpret_cast<const float4*>(&g_rec[c][tb] + q*4);
    sh[c][q*4+0]=v.x; sh[c][q*4+1]=v.y; sh[c][q*4+2]=v.z; sh[c][q*4+3]=v.w;
  }
  if (tid<128) s_ow[tid]=out_w[tid];
  else if (tid<192) s_pw[tid-128]=pw[tid-128];
  else if (tid<200) s_pb[tid-192]=pb[tid-192];
  else if (tid<208) s_g[tid-200]=ng[tid-200];
  else if (tid<216) s_nb[tid-208]=nbv[tid-208];
  else if (tid<232) s_D[tid-216]=Dv[tid-216];
  else if (tid==232) s_skip = skipp[0];
  int d=tid>>4, n=tid&15;
  float ac = -__expf(Alog[d*16+n])*1.4426950408889634f;
  float h = g_H[(b*TOTC+cg)*256+tid];
  __syncthreads();
  #pragma unroll 8
  for (int t=0;t<64;t++){
    float dl = sh[d][t];
    float a = exp2f(dl*ac);
    h = a*h + dl*sh[16+d][t]*sh[32+n][t];
    float pr = h*sh[48+n][t];
    pr += __shfl_xor_sync(0xffffffffu, pr, 8);
    pr += __shfl_xor_sync(0xffffffffu, pr, 4);
    pr += __shfl_xor_sync(0xffffffffu, pr, 2);
    pr += __shfl_xor_sync(0xffffffffu, pr, 1);
    if ((tid&15)==0) ysh[t][d]=pr;
  }
  __syncthreads();
  if (tid < 64){
    int t = tid;
    int tg = tb + t;
    float yf[16];
    #pragma unroll
    for (int dd=0;dd<16;dd++){
      float z = g_xz[16+dd][tg];
      yf[dd] = (ysh[t][dd] + sh[16+dd][t]*s_D[dd]) * siluf(z);
    }
    float o[8]; float mu=0.f;
    #pragma unroll
    for (int ch=0;ch<8;ch++){
      float acc = s_skip * g_x8[ch][tg];
      #pragma unroll
      for (int dd=0;dd<16;dd++) acc += yf[dd]*s_ow[ch*16+dd];
      o[ch]=acc; mu+=acc;
    }
    mu *= 0.125f;
    float var=0.f;
    #pragma unroll
    for (int ch=0;ch<8;ch++){ float dv=o[ch]-mu; var += dv*dv; }
    var *= 0.125f;
    float rs = rsqrtf(var + 1e-5f);
    float ln[8];
    #pragma unroll
    for (int ch=0;ch<8;ch++) ln[ch] = (o[ch]-mu)*rs*s_g[ch] + s_nb[ch];
    // scatter
    int p = cis*64 + t;
    int i = s, pp = p;
    while (pp >= c_plen[i]) { pp -= c_plen[i]; ++i; }
    int base = c_obase[i] + b*c_bs[i] + (8*s)*c_plen[i] + pp;
    #pragma unroll
    for (int j=0;j<8;j++){
      float acc = s_pb[j];
      #pragma unroll
      for (int ch=0;ch<8;ch++) acc += ln[ch]*s_pw[j*8+ch];
      out[base + j*c_plen[i]] = acc;
    }
  }
}

// ---------------- K6: whole m1 path (c5, L=64, dm=16) in one kernel ----------------
__global__ void k6_m1(const float* __restrict__ t5, const float* __restrict__ in_w,
                      const float* __restrict__ conv_w, const float* __restrict__ conv_b,
                      const float* __restrict__ xproj_w, const float* __restrict__ dt_w,
                      const float* __restrict__ dt_b, const float* __restrict__ Alog,
                      const float* __restrict__ Dv, const float* __restrict__ out_w,
                      const float* __restrict__ ng, const float* __restrict__ nbv,
                      const float* __restrict__ pw, const float* __restrict__ pb,
                      const float* __restrict__ skipp, float* __restrict__ out){
  __shared__ float s_x[64][16];
  __shared__ float s_xi[64][32];   // reused as delta after conv
  __shared__ float s_z[64][32];
  __shared__ float s_xc[64][32];
  __shared__ float s_B[64][16];
  __shared__ float s_C[64][16];
  __shared__ float s_dt[64];
  __shared__ float s_y[64][32];
  int b = blockIdx.x, tid = threadIdx.x;
  for (int i=tid;i<64*16;i+=512){
    int t=i>>4, c=i&15;
    s_x[t][c] = t5[b*3072 + (32+c)*64 + t];
  }
  __syncthreads();
  for (int i=tid;i<64*64;i+=512){     // in-proj
    int t=i>>6, j=i&63;
    float v=0.f;
    #pragma unroll
    for (int c=0;c<16;c++) v += s_x[t][c]*in_w[j*16+c];
    if (j<32) s_xi[t][j]=v; else s_z[t][j-32]=v;
  }
  __syncthreads();
  for (int i=tid;i<64*32;i+=512){     // conv + silu
    int t=i>>5, d=i&31;
    float acc = conv_b[d];
    #pragma unroll
    for (int k=0;k<4;k++){
      int tt = t-3+k;
      if (tt>=0) acc += conv_w[d*4+k]*s_xi[tt][d];
    }
    s_xc[t][d] = siluf(acc);
  }
  __syncthreads();
  for (int i=tid;i<64*33;i+=512){     // x-proj
    int t=i/33, j=i%33;
    float v=0.f;
    #pragma unroll
    for (int d=0;d<32;d++) v += s_xc[t][d]*xproj_w[j*32+d];
    if (j==0) s_dt[t]=v;
    else if (j<17) s_B[t][j-1]=v;
    else s_C[t][j-17]=v;
  }
  __syncthreads();
  for (int i=tid;i<64*32;i+=512){     // delta (overwrites s_xi)
    int t=i>>5, d=i&31;
    s_xi[t][d] = softplusf(s_dt[t]*dt_w[d] + dt_b[d]);
  }
  __syncthreads();
  {                                    // scan: thread = (d,n), 32*16 = 512 lanes
    int d=tid>>4, n=tid&15;
    float ac = -__expf(Alog[d*16+n])*1.4426950408889634f;
    float h=0.f;
    for (int t=0;t<64;t++){
      float dl = s_xi[t][d];
      float a = exp2f(dl*ac);
      h = a*h + dl*s_xc[t][d]*s_B[t][n];
      float pr = h*s_C[t][n];
      pr += __shfl_xor_sync(0xffffffffu, pr, 8);
      pr += __shfl_xor_sync(0xffffffffu, pr, 4);
      pr += __shfl_xor_sync(0xffffffffu, pr, 2);
      pr += __shfl_xor_sync(0xffffffffu, pr, 1);
      if (n==0) s_y[t][d]=pr;
    }
  }
  __syncthreads();
  if (tid<64){
    int t=tid;
    float skip = skipp[0];
    float yf[32];
    #pragma unroll
    for (int d=0;d<32;d++) yf[d] = (s_y[t][d] + s_xc[t][d]*Dv[d]) * siluf(s_z[t][d]);
    float o[16]; float mu=0.f;
    #pragma unroll
    for (int ch=0;ch<16;ch++){
      float acc = skip * s_x[t][ch];
      #pragma unroll
      for (int d=0;d<32;d++) acc += yf[d]*out_w[ch*32+d];
      o[ch]=acc; mu+=acc;
    }
    mu *= (1.0f/16.0f);
    float var=0.f;
    #pragma unroll
    for (int ch=0;ch<16;ch++){ float dv=o[ch]-mu; var+=dv*dv; }
    var *= (1.0f/16.0f);
    float rs = rsqrtf(var+1e-5f);
    float ln[16];
    #pragma unroll
    for (int ch=0;ch<16;ch++) ln[ch] = (o[ch]-mu)*rs*ng[ch]+nbv[ch];
    #pragma unroll
    for (int j=0;j<16;j++){
      float acc = pb[j];
      #pragma unroll
      for (int ch=0;ch<16;ch++) acc += ln[ch]*pw[j*16+ch];
      out[1835008 + b*3072 + (32+j)*64 + t] = acc;
    }
  }
}

// ---------------- launch ----------------
extern "C" void kernel_launch(void* const* d_in, const int* in_sizes, int n_in,
                              void* d_out, int out_size){
  (void)in_sizes; (void)n_in; (void)out_size;
  const float* t1 = (const float*)d_in[0];
  const float* t2 = (const float*)d_in[1];
  const float* t3 = (const float*)d_in[2];
  const float* t4 = (const float*)d_in[3];
  const float* t5 = (const float*)d_in[4];
  float* out = (float*)d_out;

  k1_gather<<<BTOK/256, 256>>>(t1,t2,t3,t4,t5,(const float*)d_in[5]);
  k2_pre  <<<BTOK/256, 256>>>((const float*)d_in[6],(const float*)d_in[7],
                              (const float*)d_in[8],(const float*)d_in[9],
                              (const float*)d_in[10]);
  k3_scanA<<<NB*TOTC, 256>>>((const float*)d_in[11]);
  k4_chunk<<<32, 256>>>();
  k5_scanC<<<NB*TOTC, 256>>>((const float*)d_in[11],(const float*)d_in[13],
                             (const float*)d_in[12],(const float*)d_in[23],
                             (const float*)d_in[24],(const float*)d_in[25],
                             (const float*)d_in[26],(const float*)d_in[31], out);
  k6_m1   <<<NB, 512>>>(t5,(const float*)d_in[14],(const float*)d_in[15],
                        (const float*)d_in[16],(const float*)d_in[17],
                        (const float*)d_in[18],(const float*)d_in[19],
                        (const float*)d_in[20],(const float*)d_in[21],
                        (const float*)d_in[22],(const float*)d_in[27],
                        (const float*)d_in[28],(const float*)d_in[29],
                        (const float*)d_in[30],(const float*)d_in[31], out);
}

// round 5
// speedup vs baseline: 1.2509x; 1.2509x over previous
#include <cuda_runtime.h>
#include <math.h>

// ---------------- problem geometry ----------------
#define LTOT 28928          // tokens per batch across seqs 0..3
#define BTOK 231424         // 8 * LTOT
#define TOTC 452            // chunks (T=64) per batch: 341+85+21+5
#define NB   8

// ---------------- static device scratch ----------------
__device__ float g_x8[8][BTOK];     // gathered dm=8 input tokens (channel-major)
__device__ float g_xz[32][BTOK];    // in-proj output: xi (0..15), z (16..31)
__device__ float g_rec[64][BTOK];   // per-token record: delta(0..15) xc(16..31) B(32..47) C(48..63)
__device__ float g_P[NB*TOTC*256];  // per-chunk product of a
__device__ float g_S[NB*TOTC*256];  // per-chunk local scan end (h_start=0)
__device__ float g_H[NB*TOTC*256];  // h_start per chunk

__constant__ int c_plen[5]  = {16384,4096,1024,256,64};      // spatial size per tensor (= ch stride)
__constant__ int c_bs[5]    = {131072,65536,24576,8192,3072};// batch stride per tensor
__constant__ int c_obase[5] = {0,1048576,1572864,1769472,1835008};
__constant__ int c_O[4]     = {0,21824,27264,28608};         // seq offsets within a batch
__constant__ int c_CB[4]    = {0,341,426,447};               // chunk base per seq
__constant__ int c_NC[4]    = {341,85,21,5};                 // chunks per seq

__device__ __forceinline__ float siluf(float x){ return x * (1.0f/(1.0f+__expf(-x))); }
__device__ __forceinline__ float softplusf(float x){ return (x>20.0f)? x : log1pf(__expf(x)); }

// ---------------- K1: gather + in-projection ----------------
__global__ void k1_gather(const float* __restrict__ t1, const float* __restrict__ t2,
                          const float* __restrict__ t3, const float* __restrict__ t4,
                          const float* __restrict__ t5, const float* __restrict__ in_w){
  __shared__ float s_w[256]; // (32,8)
  int tid = threadIdx.x;
  if (tid < 256) s_w[tid] = in_w[tid];
  __syncthreads();
  int tg = blockIdx.x*256 + tid;           // < BTOK exactly (904 blocks)
  int b = tg / LTOT, r = tg % LTOT;
  int s = (r>=21824)+(r>=27264)+(r>=28608);
  int p = r - c_O[s];
  int i = s, pp = p;
  while (pp >= c_plen[i]) { pp -= c_plen[i]; ++i; }
  const float* tp = (i==0)?t1:(i==1)?t2:(i==2)?t3:(i==3)?t4:t5;
  int base = b*c_bs[i] + (8*s)*c_plen[i] + pp;
  float x[8];
  #pragma unroll
  for (int c=0;c<8;c++){ x[c] = tp[base + c*c_plen[i]]; g_x8[c][tg] = x[c]; }
  #pragma unroll
  for (int j=0;j<32;j++){
    float v = 0.f;
    #pragma unroll
    for (int c=0;c<8;c++) v += x[c]*s_w[j*8+c];
    g_xz[j][tg] = v;
  }
}

// ---------------- K2: conv + silu + x-proj + softplus -> records ----------------
__global__ void k2_pre(const float* __restrict__ conv_w, const float* __restrict__ conv_b,
                       const float* __restrict__ xproj_w, const float* __restrict__ dt_w,
                       const float* __restrict__ dt_b){
  __shared__ float s_xp[33*16];
  __shared__ float s_cw[64], s_cb[16], s_dtw[16], s_dtb[16];
  int tid = threadIdx.x;
  for (int i=tid;i<33*16;i+=256) s_xp[i]=xproj_w[i];
  if (tid<64) s_cw[tid]=conv_w[tid];
  if (tid<16){ s_cb[tid]=conv_b[tid]; s_dtw[tid]=dt_w[tid]; s_dtb[tid]=dt_b[tid]; }
  __syncthreads();
  int tg = blockIdx.x*256+tid;
  int r = tg % LTOT;
  int s = (r>=21824)+(r>=27264)+(r>=28608);
  int p = r - c_O[s];
  float xc[16];
  #pragma unroll
  for (int d=0;d<16;d++){
    float acc = s_cb[d];
    #pragma unroll
    for (int k=0;k<4;k++){
      int back = 3-k;
      float v = (p>=back)? g_xz[d][tg-back] : 0.0f;
      acc += s_cw[d*4+k]*v;
    }
    xc[d] = siluf(acc);
    g_rec[16+d][tg] = xc[d];
  }
  float dt = 0.f;
  #pragma unroll
  for (int d=0;d<16;d++) dt += xc[d]*s_xp[d];   // xproj row 0
  #pragma unroll
  for (int d=0;d<16;d++) g_rec[d][tg] = softplusf(dt*s_dtw[d]+s_dtb[d]);
  #pragma unroll
  for (int j=0;j<16;j++){
    float bv=0.f, cv=0.f;
    #pragma unroll
    for (int d=0;d<16;d++){ bv += xc[d]*s_xp[(1+j)*16+d]; cv += xc[d]*s_xp[(17+j)*16+d]; }
    g_rec[32+j][tg]=bv; g_rec[48+j][tg]=cv;
  }
}

// ---------------- K3: phase A — per-chunk (P, S) ----------------
__global__ void k3_scanA(const float* __restrict__ Alog){
  int blk = blockIdx.x;
  int b = blk / TOTC, cg = blk % TOTC;
  int s = (cg>=341)+(cg>=426)+(cg>=447);
  int tb = b*LTOT + c_O[s] + (cg - c_CB[s])*64;
  __shared__ float sh[48][65];
  int tid = threadIdx.x;
  for (int i=tid;i<48*16;i+=256){
    int c=i>>4, q=i&15;
    float4 v = *reinterpret_cast<const float4*>(&g_rec[c][tb] + q*4);
    sh[c][q*4+0]=v.x; sh[c][q*4+1]=v.y; sh[c][q*4+2]=v.z; sh[c][q*4+3]=v.w;
  }
  int d = tid>>4, n = tid&15;
  float ac = -__expf(Alog[d*16+n])*1.4426950408889634f;
  __syncthreads();
  float h=0.f, P=1.f;
  #pragma unroll 8
  for (int t=0;t<64;t++){
    float dl = sh[d][t];
    float a = exp2f(dl*ac);
    h = a*h + dl*sh[16+d][t]*sh[32+n][t];
    P *= a;
  }
  int idx = (b*TOTC+cg)*256+tid;
  g_P[idx]=P; g_S[idx]=h;
}

// ---------------- K4: chunk-prefix scan -> h_start per chunk ----------------
// Latency fix: batch-load UNR chunks' (P,S) into registers (independent,
// coalesced loads, MLP=2*UNR) before running the serial FMA chain.
__global__ void k4_chunk(){
  constexpr int UNR = 16;
  int b = blockIdx.x >> 2, s = blockIdx.x & 3;
  int tid = threadIdx.x;
  float H = 0.f;
  int base = (b*TOTC + c_CB[s])*256 + tid;
  int nc = c_NC[s];
  for (int c0=0;c0<nc;c0+=UNR){
    int m = nc - c0; if (m > UNR) m = UNR;
    float P[UNR], S[UNR];
    #pragma unroll
    for (int u=0;u<UNR;u++){
      if (u<m){
        int idx = base + (c0+u)*256;
        P[u]=g_P[idx]; S[u]=g_S[idx];
      }
    }
    #pragma unroll
    for (int u=0;u<UNR;u++){
      if (u<m){
        g_H[base + (c0+u)*256] = H;
        H = P[u]*H + S[u];
      }
    }
  }
}

// ---------------- K5: phase C — scan replay + full epilogue + scatter ----------------
__global__ void k5_scanC(const float* __restrict__ Alog, const float* __restrict__ out_w,
                         const float* __restrict__ Dv, const float* __restrict__ ng,
                         const float* __restrict__ nbv, const float* __restrict__ pw,
                         const float* __restrict__ pb, const float* __restrict__ skipp,
                         float* __restrict__ out){
  int blk = blockIdx.x;
  int b = blk / TOTC, cg = blk % TOTC;
  int s = (cg>=341)+(cg>=426)+(cg>=447);
  int cis = cg - c_CB[s];
  int tb = b*LTOT + c_O[s] + cis*64;
  __shared__ float sh[64][65];
  __shared__ float ysh[64][16];
  __shared__ float s_ow[128], s_pw[64], s_pb[8], s_g[8], s_nb[8], s_D[16];
  __shared__ float s_skip;
  int tid = threadIdx.x;
  for (int i=tid;i<64*16;i+=256){
    int c=i>>4, q=i&15;
    float4 v = *reinterpret_cast<const float4*>(&g_rec[c][tb] + q*4);
    sh[c][q*4+0]=v.x; sh[c][q*4+1]=v.y; sh[c][q*4+2]=v.z; sh[c][q*4+3]=v.w;
  }
  if (tid<128) s_ow[tid]=out_w[tid];
  else if (tid<192) s_pw[tid-128]=pw[tid-128];
  else if (tid<200) s_pb[tid-192]=pb[tid-192];
  else if (tid<208) s_g[tid-200]=ng[tid-200];
  else if (tid<216) s_nb[tid-208]=nbv[tid-208];
  else if (tid<232) s_D[tid-216]=Dv[tid-216];
  else if (tid==232) s_skip = skipp[0];
  int d=tid>>4, n=tid&15;
  float ac = -__expf(Alog[d*16+n])*1.4426950408889634f;
  float h = g_H[(b*TOTC+cg)*256+tid];
  __syncthreads();
  #pragma unroll 8
  for (int t=0;t<64;t++){
    float dl = sh[d][t];
    float a = exp2f(dl*ac);
    h = a*h + dl*sh[16+d][t]*sh[32+n][t];
    float pr = h*sh[48+n][t];
    pr += __shfl_xor_sync(0xffffffffu, pr, 8);
    pr += __shfl_xor_sync(0xffffffffu, pr, 4);
    pr += __shfl_xor_sync(0xffffffffu, pr, 2);
    pr += __shfl_xor_sync(0xffffffffu, pr, 1);
    if ((tid&15)==0) ysh[t][d]=pr;
  }
  __syncthreads();
  if (tid < 64){
    int t = tid;
    int tg = tb + t;
    float yf[16];
    #pragma unroll
    for (int dd=0;dd<16;dd++){
      float z = g_xz[16+dd][tg];
      yf[dd] = (ysh[t][dd] + sh[16+dd][t]*s_D[dd]) * siluf(z);
    }
    float o[8]; float mu=0.f;
    #pragma unroll
    for (int ch=0;ch<8;ch++){
      float acc = s_skip * g_x8[ch][tg];
      #pragma unroll
      for (int dd=0;dd<16;dd++) acc += yf[dd]*s_ow[ch*16+dd];
      o[ch]=acc; mu+=acc;
    }
    mu *= 0.125f;
    float var=0.f;
    #pragma unroll
    for (int ch=0;ch<8;ch++){ float dv=o[ch]-mu; var += dv*dv; }
    var *= 0.125f;
    float rs = rsqrtf(var + 1e-5f);
    float ln[8];
    #pragma unroll
    for (int ch=0;ch<8;ch++) ln[ch] = (o[ch]-mu)*rs*s_g[ch] + s_nb[ch];
    // scatter
    int p = cis*64 + t;
    int i = s, pp = p;
    while (pp >= c_plen[i]) { pp -= c_plen[i]; ++i; }
    int base = c_obase[i] + b*c_bs[i] + (8*s)*c_plen[i] + pp;
    #pragma unroll
    for (int j=0;j<8;j++){
      float acc = s_pb[j];
      #pragma unroll
      for (int ch=0;ch<8;ch++) acc += ln[ch]*s_pw[j*8+ch];
      out[base + j*c_plen[i]] = acc;
    }
  }
}

// ---------------- K6: whole m1 path (c5, L=64, dm=16) in one kernel ----------------
__global__ void k6_m1(const float* __restrict__ t5, const float* __restrict__ in_w,
                      const float* __restrict__ conv_w, const float* __restrict__ conv_b,
                      const float* __restrict__ xproj_w, const float* __restrict__ dt_w,
                      const float* __restrict__ dt_b, const float* __restrict__ Alog,
                      const float* __restrict__ Dv, const float* __restrict__ out_w,
                      const float* __restrict__ ng, const float* __restrict__ nbv,
                      const float* __restrict__ pw, const float* __restrict__ pb,
                      const float* __restrict__ skipp, float* __restrict__ out){
  __shared__ float s_x[64][16];
  __shared__ float s_xi[64][32];   // reused as delta after conv
  __shared__ float s_z[64][32];
  __shared__ float s_xc[64][32];
  __shared__ float s_B[64][16];
  __shared__ float s_C[64][16];
  __shared__ float s_dt[64];
  __shared__ float s_y[64][32];
  int b = blockIdx.x, tid = threadIdx.x;
  for (int i=tid;i<64*16;i+=512){
    int t=i>>4, c=i&15;
    s_x[t][c] = t5[b*3072 + (32+c)*64 + t];
  }
  __syncthreads();
  for (int i=tid;i<64*64;i+=512){     // in-proj
    int t=i>>6, j=i&63;
    float v=0.f;
    #pragma unroll
    for (int c=0;c<16;c++) v += s_x[t][c]*in_w[j*16+c];
    if (j<32) s_xi[t][j]=v; else s_z[t][j-32]=v;
  }
  __syncthreads();
  for (int i=tid;i<64*32;i+=512){     // conv + silu
    int t=i>>5, d=i&31;
    float acc = conv_b[d];
    #pragma unroll
    for (int k=0;k<4;k++){
      int tt = t-3+k;
      if (tt>=0) acc += conv_w[d*4+k]*s_xi[tt][d];
    }
    s_xc[t][d] = siluf(acc);
  }
  __syncthreads();
  for (int i=tid;i<64*33;i+=512){     // x-proj
    int t=i/33, j=i%33;
    float v=0.f;
    #pragma unroll
    for (int d=0;d<32;d++) v += s_xc[t][d]*xproj_w[j*32+d];
    if (j==0) s_dt[t]=v;
    else if (j<17) s_B[t][j-1]=v;
    else s_C[t][j-17]=v;
  }
  __syncthreads();
  for (int i=tid;i<64*32;i+=512){     // delta (overwrites s_xi)
    int t=i>>5, d=i&31;
    s_xi[t][d] = softplusf(s_dt[t]*dt_w[d] + dt_b[d]);
  }
  __syncthreads();
  {                                    // scan: thread = (d,n), 32*16 = 512 lanes
    int d=tid>>4, n=tid&15;
    float ac = -__expf(Alog[d*16+n])*1.4426950408889634f;
    float h=0.f;
    for (int t=0;t<64;t++){
      float dl = s_xi[t][d];
      float a = exp2f(dl*ac);
      h = a*h + dl*s_xc[t][d]*s_B[t][n];
      float pr = h*s_C[t][n];
      pr += __shfl_xor_sync(0xffffffffu, pr, 8);
      pr += __shfl_xor_sync(0xffffffffu, pr, 4);
      pr += __shfl_xor_sync(0xffffffffu, pr, 2);
      pr += __shfl_xor_sync(0xffffffffu, pr, 1);
      if (n==0) s_y[t][d]=pr;
    }
  }
  __syncthreads();
  if (tid<64){
    int t=tid;
    float skip = skipp[0];
    float yf[32];
    #pragma unroll
    for (int d=0;d<32;d++) yf[d] = (s_y[t][d] + s_xc[t][d]*Dv[d]) * siluf(s_z[t][d]);
    float o[16]; float mu=0.f;
    #pragma unroll
    for (int ch=0;ch<16;ch++){
      float acc = skip * s_x[t][ch];
      #pragma unroll
      for (int d=0;d<32;d++) acc += yf[d]*out_w[ch*32+d];
      o[ch]=acc; mu+=acc;
    }
    mu *= (1.0f/16.0f);
    float var=0.f;
    #pragma unroll
    for (int ch=0;ch<16;ch++){ float dv=o[ch]-mu; var+=dv*dv; }
    var *= (1.0f/16.0f);
    float rs = rsqrtf(var+1e-5f);
    float ln[16];
    #pragma unroll
    for (int ch=0;ch<16;ch++) ln[ch] = (o[ch]-mu)*rs*ng[ch]+nbv[ch];
    #pragma unroll
    for (int j=0;j<16;j++){
      float acc = pb[j];
      #pragma unroll
      for (int ch=0;ch<16;ch++) acc += ln[ch]*pw[j*16+ch];
      out[1835008 + b*3072 + (32+j)*64 + t] = acc;
    }
  }
}

// ---------------- launch ----------------
extern "C" void kernel_launch(void* const* d_in, const int* in_sizes, int n_in,
                              void* d_out, int out_size){
  (void)in_sizes; (void)n_in; (void)out_size;
  const float* t1 = (const float*)d_in[0];
  const float* t2 = (const float*)d_in[1];
  const float* t3 = (const float*)d_in[2];
  const float* t4 = (const float*)d_in[3];
  const float* t5 = (const float*)d_in[4];
  float* out = (float*)d_out;

  k1_gather<<<BTOK/256, 256>>>(t1,t2,t3,t4,t5,(const float*)d_in[5]);
  k2_pre  <<<BTOK/256, 256>>>((const float*)d_in[6],(const float*)d_in[7],
                              (const float*)d_in[8],(const float*)d_in[9],
                              (const float*)d_in[10]);
  k3_scanA<<<NB*TOTC, 256>>>((const float*)d_in[11]);
  k4_chunk<<<32, 256>>>();
  k5_scanC<<<NB*TOTC, 256>>>((const float*)d_in[11],(const float*)d_in[13],
                             (const float*)d_in[12],(const float*)d_in[23],
                             (const float*)d_in[24],(const float*)d_in[25],
                             (const float*)d_in[26],(const float*)d_in[31], out);
  k6_m1   <<<NB, 512>>>(t5,(const float*)d_in[14],(const float*)d_in[15],
                        (const float*)d_in[16],(const float*)d_in[17],
                        (const float*)d_in[18],(const float*)d_in[19],
                        (const float*)d_in[20],(const float*)d_in[21],
                        (const float*)d_in[22],(const float*)d_in[27],
                        (const float*)d_in[28],(const float*)d_in[29],
                        (const float*)d_in[30],(const float*)d_in[31], out);
}

// round 6
// speedup vs baseline: 1.5095x; 1.2068x over previous
#include <cuda_runtime.h>
#include <math.h>

// ---------------- problem geometry ----------------
#define LTOT 28928          // tokens per batch across seqs 0..3
#define BTOK 231424         // 8 * LTOT
#define TOTC 452            // chunks (T=64) per batch: 341+85+21+5
#define NB   8

// ---------------- static device scratch ----------------
__device__ float g_x8[8][BTOK];     // gathered dm=8 input tokens (channel-major)
__device__ float g_xz[32][BTOK];    // in-proj output: xi (0..15), z (16..31)
__device__ float g_P[NB*TOTC*256];  // per-chunk product of a
__device__ float g_S[NB*TOTC*256];  // per-chunk local scan end (h_start=0)
__device__ float g_H[NB*TOTC*256];  // h_start per chunk

__constant__ int c_plen[5]  = {16384,4096,1024,256,64};      // spatial size per tensor (= ch stride)
__constant__ int c_bs[5]    = {131072,65536,24576,8192,3072};// batch stride per tensor
__constant__ int c_obase[5] = {0,1048576,1572864,1769472,1835008};
__constant__ int c_O[4]     = {0,21824,27264,28608};         // seq offsets within a batch
__constant__ int c_CB[4]    = {0,341,426,447};               // chunk base per seq
__constant__ int c_NC[4]    = {341,85,21,5};                 // chunks per seq

__device__ __forceinline__ float siluf(float x){ return x * (1.0f/(1.0f+__expf(-x))); }
__device__ __forceinline__ float softplusf(float x){ return (x>20.0f)? x : log1pf(__expf(x)); }

// ---------------- K1: gather + in-projection ----------------
__global__ void k1_gather(const float* __restrict__ t1, const float* __restrict__ t2,
                          const float* __restrict__ t3, const float* __restrict__ t4,
                          const float* __restrict__ t5, const float* __restrict__ in_w){
  __shared__ float s_w[256]; // (32,8)
  int tid = threadIdx.x;
  if (tid < 256) s_w[tid] = in_w[tid];
  __syncthreads();
  int tg = blockIdx.x*256 + tid;           // < BTOK exactly (904 blocks)
  int b = tg / LTOT, r = tg % LTOT;
  int s = (r>=21824)+(r>=27264)+(r>=28608);
  int p = r - c_O[s];
  int i = s, pp = p;
  while (pp >= c_plen[i]) { pp -= c_plen[i]; ++i; }
  const float* tp = (i==0)?t1:(i==1)?t2:(i==2)?t3:(i==3)?t4:t5;
  int base = b*c_bs[i] + (8*s)*c_plen[i] + pp;
  float x[8];
  #pragma unroll
  for (int c=0;c<8;c++){ x[c] = tp[base + c*c_plen[i]]; g_x8[c][tg] = x[c]; }
  #pragma unroll
  for (int j=0;j<32;j++){
    float v = 0.f;
    #pragma unroll
    for (int c=0;c<8;c++) v += x[c]*s_w[j*8+c];
    g_xz[j][tg] = v;
  }
}

// ======= shared record-recompute used by fused scan kernels ===============
// Layouts: xi[d][j] holds token tb-4+j  (token t -> j=t+4; conv taps j=t+1..t+4)
//          del/xcs/Bs/Cs: [chan][t] with stride 66 (conflict-free)
struct RecSmem {
  float xi[16][68];
  float del[16][66], xcs[16][66], Bs[16][66], Cs[16][66];
  float dtv[64];
  float xp[33*16];
  float cw[64], cb[16], dtw[16], dtb[16];
};

__device__ __forceinline__ void rec_compute(RecSmem& S, int tid, int tb, int cis,
    const float* __restrict__ xproj_w, const float* __restrict__ conv_w,
    const float* __restrict__ conv_b,  const float* __restrict__ dt_w,
    const float* __restrict__ dt_b){
  // params
  for (int i=tid;i<528;i+=256) S.xp[i]=xproj_w[i];
  if (tid<64) S.cw[tid]=conv_w[tid];
  if (tid<16){ S.cb[tid]=conv_b[tid]; S.dtw[tid]=dt_w[tid]; S.dtb[tid]=dt_b[tid]; }
  // xi halo load: 16 rows x 17 float4 (tokens tb-4 .. tb+63)
  for (int i=tid;i<272;i+=256){
    int d=i/17, q=i%17;
    float4 v;
    if (cis==0 && q==0) v = make_float4(0.f,0.f,0.f,0.f);
    else v = *reinterpret_cast<const float4*>(&g_xz[d][tb-4+q*4]);
    S.xi[d][q*4+0]=v.x; S.xi[d][q*4+1]=v.y; S.xi[d][q*4+2]=v.z; S.xi[d][q*4+3]=v.w;
  }
  __syncthreads();
  // conv + silu -> xcs
  #pragma unroll
  for (int k=0;k<4;k++){
    int idx = tid + k*256;
    int d = idx>>6, t = idx&63;
    float acc = S.cb[d];
    #pragma unroll
    for (int kk=0;kk<4;kk++) acc += S.cw[d*4+kk]*S.xi[d][t+1+kk];
    S.xcs[d][t] = siluf(acc);
  }
  __syncthreads();
  // dt row
  if (tid<64){
    float v=0.f;
    #pragma unroll
    for (int d=0;d<16;d++) v += S.xcs[d][tid]*S.xp[d];
    S.dtv[tid]=v;
  }
  __syncthreads();
  // B, C
  #pragma unroll
  for (int k=0;k<8;k++){
    int idx = tid + k*256;          // 0..2047
    int t = idx&63, j = idx>>6;     // j 0..31
    float v=0.f;
    #pragma unroll
    for (int d=0;d<16;d++) v += S.xcs[d][t]*S.xp[(1+j)*16+d];
    if (j<16) S.Bs[j][t]=v; else S.Cs[j-16][t]=v;
  }
  // delta
  #pragma unroll
  for (int k=0;k<4;k++){
    int idx = tid + k*256;
    int d = idx>>6, t = idx&63;
    S.del[d][t] = softplusf(S.dtv[t]*S.dtw[d]+S.dtb[d]);
  }
  __syncthreads();
}

// ---------------- K3: fused record recompute + phase A (P,S) --------------
__global__ void k3_scanA(const float* __restrict__ xproj_w, const float* __restrict__ conv_w,
                         const float* __restrict__ conv_b, const float* __restrict__ dt_w,
                         const float* __restrict__ dt_b, const float* __restrict__ Alog){
  __shared__ RecSmem S;
  int blk = blockIdx.x;
  int b = blk / TOTC, cg = blk % TOTC;
  int s = (cg>=341)+(cg>=426)+(cg>=447);
  int cis = cg - c_CB[s];
  int tb = b*LTOT + c_O[s] + cis*64;
  int tid = threadIdx.x;
  float ac = -__expf(Alog[tid])*1.4426950408889634f;
  rec_compute(S, tid, tb, cis, xproj_w, conv_w, conv_b, dt_w, dt_b);
  int d = tid>>4, n = tid&15;
  float h=0.f, P=1.f;
  #pragma unroll 8
  for (int t=0;t<64;t++){
    float dl = S.del[d][t];
    float a = exp2f(dl*ac);
    h = a*h + dl*S.xcs[d][t]*S.Bs[n][t];
    P *= a;
  }
  int idx = (b*TOTC+cg)*256+tid;
  g_P[idx]=P; g_S[idx]=h;
}

// ---------------- K4: chunk-prefix scan, software-pipelined ----------------
__global__ void k4_chunk(){
  constexpr int U = 16;
  int b = blockIdx.x >> 2, s = blockIdx.x & 3;
  int tid = threadIdx.x;
  int base = (b*TOTC + c_CB[s])*256 + tid;
  int nc = c_NC[s];
  int nbatch = (nc + U - 1)/U;
  float PA[U],SA[U],PB[U],SB[U];
  #pragma unroll
  for (int u=0;u<U;u++){
    if (u<nc){ int idx=base+u*256; PA[u]=g_P[idx]; SA[u]=g_S[idx]; }
    else { PA[u]=1.f; SA[u]=0.f; }
  }
  float H=0.f;
  for (int bi=0; bi<nbatch; bi+=2){
    if (bi+1<nbatch){
      #pragma unroll
      for (int u=0;u<U;u++){
        int c=(bi+1)*U+u;
        if (c<nc){ int idx=base+c*256; PB[u]=g_P[idx]; SB[u]=g_S[idx]; }
        else { PB[u]=1.f; SB[u]=0.f; }
      }
    }
    #pragma unroll
    for (int u=0;u<U;u++){
      int c=bi*U+u;
      if (c<nc){ g_H[base+c*256]=H; H = PA[u]*H + SA[u]; }
    }
    if (bi+2<nbatch){
      #pragma unroll
      for (int u=0;u<U;u++){
        int c=(bi+2)*U+u;
        if (c<nc){ int idx=base+c*256; PA[u]=g_P[idx]; SA[u]=g_S[idx]; }
        else { PA[u]=1.f; SA[u]=0.f; }
      }
    }
    if (bi+1<nbatch){
      #pragma unroll
      for (int u=0;u<U;u++){
        int c=(bi+1)*U+u;
        if (c<nc){ g_H[base+c*256]=H; H = PB[u]*H + SB[u]; }
      }
    }
  }
}

// ---------------- K5: fused recompute + phase C + epilogue + scatter -------
struct K5Smem {
  RecSmem R;
  float ysh[64][16];
  float zsh[16][66];
  float x8sh[8][66];
  float ow[128], pwm[64], pbv[8], gv[8], nbvv[8], Dvv[16];
  float skip;
};

__global__ void k5_scanC(const float* __restrict__ xproj_w, const float* __restrict__ conv_w,
                         const float* __restrict__ conv_b, const float* __restrict__ dt_w,
                         const float* __restrict__ dt_b, const float* __restrict__ Alog,
                         const float* __restrict__ out_w, const float* __restrict__ Dv,
                         const float* __restrict__ ng, const float* __restrict__ nbv,
                         const float* __restrict__ pw, const float* __restrict__ pb,
                         const float* __restrict__ skipp, float* __restrict__ out){
  __shared__ K5Smem S;
  int blk = blockIdx.x;
  int b = blk / TOTC, cg = blk % TOTC;
  int s = (cg>=341)+(cg>=426)+(cg>=447);
  int cis = cg - c_CB[s];
  int tb = b*LTOT + c_O[s] + cis*64;
  int tid = threadIdx.x;
  float ac = -__expf(Alog[tid])*1.4426950408889634f;
  float h = g_H[(b*TOTC+cg)*256+tid];
  // epilogue params + z/x8 staging (before first sync inside rec_compute is fine:
  // they touch disjoint smem and are synced by rec_compute's barriers)
  {
    int d4=tid>>4, q4=tid&15;  // 256 = 16x16 -> z staging
    float4 v = *reinterpret_cast<const float4*>(&g_xz[16+d4][tb+q4*4]);
    S.zsh[d4][q4*4+0]=v.x; S.zsh[d4][q4*4+1]=v.y; S.zsh[d4][q4*4+2]=v.z; S.zsh[d4][q4*4+3]=v.w;
    if (tid<128){
      int d8=tid>>4, q8=tid&15;
      float4 w = *reinterpret_cast<const float4*>(&g_x8[d8][tb+q8*4]);
      S.x8sh[d8][q8*4+0]=w.x; S.x8sh[d8][q8*4+1]=w.y; S.x8sh[d8][q8*4+2]=w.z; S.x8sh[d8][q8*4+3]=w.w;
    } else {
      int u = tid-128;
      if (u<128) S.ow[u]=out_w[u];
    }
    if (tid<64) S.pwm[tid]=pw[tid];
    else if (tid<72) S.pbv[tid-64]=pb[tid-64];
    else if (tid<80) S.gv[tid-72]=ng[tid-72];
    else if (tid<88) S.nbvv[tid-80]=nbv[tid-80];
    else if (tid<104) S.Dvv[tid-88]=Dv[tid-88];
    else if (tid==104) S.skip = skipp[0];
  }
  rec_compute(S.R, tid, tb, cis, xproj_w, conv_w, conv_b, dt_w, dt_b);
  int d=tid>>4, n=tid&15;
  #pragma unroll 8
  for (int t=0;t<64;t++){
    float dl = S.R.del[d][t];
    float a = exp2f(dl*ac);
    h = a*h + dl*S.R.xcs[d][t]*S.R.Bs[n][t];
    float pr = h*S.R.Cs[n][t];
    pr += __shfl_xor_sync(0xffffffffu, pr, 8);
    pr += __shfl_xor_sync(0xffffffffu, pr, 4);
    pr += __shfl_xor_sync(0xffffffffu, pr, 2);
    pr += __shfl_xor_sync(0xffffffffu, pr, 1);
    if ((tid&15)==0) S.ysh[t][d]=pr;
  }
  __syncthreads();
  if (tid < 64){
    int t = tid;
    float yf[16];
    #pragma unroll
    for (int dd=0;dd<16;dd++){
      float z = S.zsh[dd][t];
      yf[dd] = (S.ysh[t][dd] + S.R.xcs[dd][t]*S.Dvv[dd]) * siluf(z);
    }
    float o[8]; float mu=0.f;
    #pragma unroll
    for (int ch=0;ch<8;ch++){
      float acc = S.skip * S.x8sh[ch][t];
      #pragma unroll
      for (int dd=0;dd<16;dd++) acc += yf[dd]*S.ow[ch*16+dd];
      o[ch]=acc; mu+=acc;
    }
    mu *= 0.125f;
    float var=0.f;
    #pragma unroll
    for (int ch=0;ch<8;ch++){ float dv=o[ch]-mu; var += dv*dv; }
    var *= 0.125f;
    float rs = rsqrtf(var + 1e-5f);
    float ln[8];
    #pragma unroll
    for (int ch=0;ch<8;ch++) ln[ch] = (o[ch]-mu)*rs*S.gv[ch] + S.nbvv[ch];
    // scatter
    int p = cis*64 + t;
    int i = s, pp = p;
    while (pp >= c_plen[i]) { pp -= c_plen[i]; ++i; }
    int base = c_obase[i] + b*c_bs[i] + (8*s)*c_plen[i] + pp;
    #pragma unroll
    for (int j=0;j<8;j++){
      float acc = S.pbv[j];
      #pragma unroll
      for (int ch=0;ch<8;ch++) acc += ln[ch]*S.pwm[j*8+ch];
      out[base + j*c_plen[i]] = acc;
    }
  }
}

// ---------------- K6: whole m1 path (c5, L=64, dm=16) in one kernel ----------------
__global__ void k6_m1(const float* __restrict__ t5, const float* __restrict__ in_w,
                      const float* __restrict__ conv_w, const float* __restrict__ conv_b,
                      const float* __restrict__ xproj_w, const float* __restrict__ dt_w,
                      const float* __restrict__ dt_b, const float* __restrict__ Alog,
                      const float* __restrict__ Dv, const float* __restrict__ out_w,
                      const float* __restrict__ ng, const float* __restrict__ nbv,
                      const float* __restrict__ pw, const float* __restrict__ pb,
                      const float* __restrict__ skipp, float* __restrict__ out){
  __shared__ float s_x[64][16];
  __shared__ float s_xi[64][32];   // reused as delta after conv
  __shared__ float s_z[64][32];
  __shared__ float s_xc[64][32];
  __shared__ float s_B[64][16];
  __shared__ float s_C[64][16];
  __shared__ float s_dt[64];
  __shared__ float s_y[64][32];
  int b = blockIdx.x, tid = threadIdx.x;
  for (int i=tid;i<64*16;i+=512){
    int t=i>>4, c=i&15;
    s_x[t][c] = t5[b*3072 + (32+c)*64 + t];
  }
  __syncthreads();
  for (int i=tid;i<64*64;i+=512){     // in-proj
    int t=i>>6, j=i&63;
    float v=0.f;
    #pragma unroll
    for (int c=0;c<16;c++) v += s_x[t][c]*in_w[j*16+c];
    if (j<32) s_xi[t][j]=v; else s_z[t][j-32]=v;
  }
  __syncthreads();
  for (int i=tid;i<64*32;i+=512){     // conv + silu
    int t=i>>5, d=i&31;
    float acc = conv_b[d];
    #pragma unroll
    for (int k=0;k<4;k++){
      int tt = t-3+k;
      if (tt>=0) acc += conv_w[d*4+k]*s_xi[tt][d];
    }
    s_xc[t][d] = siluf(acc);
  }
  __syncthreads();
  for (int i=tid;i<64*33;i+=512){     // x-proj
    int t=i/33, j=i%33;
    float v=0.f;
    #pragma unroll
    for (int d=0;d<32;d++) v += s_xc[t][d]*xproj_w[j*32+d];
    if (j==0) s_dt[t]=v;
    else if (j<17) s_B[t][j-1]=v;
    else s_C[t][j-17]=v;
  }
  __syncthreads();
  for (int i=tid;i<64*32;i+=512){     // delta (overwrites s_xi)
    int t=i>>5, d=i&31;
    s_xi[t][d] = softplusf(s_dt[t]*dt_w[d] + dt_b[d]);
  }
  __syncthreads();
  {                                    // scan: thread = (d,n), 32*16 = 512 lanes
    int d=tid>>4, n=tid&15;
    float ac = -__expf(Alog[d*16+n])*1.4426950408889634f;
    float h=0.f;
    for (int t=0;t<64;t++){
      float dl = s_xi[t][d];
      float a = exp2f(dl*ac);
      h = a*h + dl*s_xc[t][d]*s_B[t][n];
      float pr = h*s_C[t][n];
      pr += __shfl_xor_sync(0xffffffffu, pr, 8);
      pr += __shfl_xor_sync(0xffffffffu, pr, 4);
      pr += __shfl_xor_sync(0xffffffffu, pr, 2);
      pr += __shfl_xor_sync(0xffffffffu, pr, 1);
      if (n==0) s_y[t][d]=pr;
    }
  }
  __syncthreads();
  if (tid<64){
    int t=tid;
    float skip = skipp[0];
    float yf[32];
    #pragma unroll
    for (int d=0;d<32;d++) yf[d] = (s_y[t][d] + s_xc[t][d]*Dv[d]) * siluf(s_z[t][d]);
    float o[16]; float mu=0.f;
    #pragma unroll
    for (int ch=0;ch<16;ch++){
      float acc = skip * s_x[t][ch];
      #pragma unroll
      for (int d=0;d<32;d++) acc += yf[d]*out_w[ch*32+d];
      o[ch]=acc; mu+=acc;
    }
    mu *= (1.0f/16.0f);
    float var=0.f;
    #pragma unroll
    for (int ch=0;ch<16;ch++){ float dv=o[ch]-mu; var+=dv*dv; }
    var *= (1.0f/16.0f);
    float rs = rsqrtf(var+1e-5f);
    float ln[16];
    #pragma unroll
    for (int ch=0;ch<16;ch++) ln[ch] = (o[ch]-mu)*rs*ng[ch]+nbv[ch];
    #pragma unroll
    for (int j=0;j<16;j++){
      float acc = pb[j];
      #pragma unroll
      for (int ch=0;ch<16;ch++) acc += ln[ch]*pw[j*16+ch];
      out[1835008 + b*3072 + (32+j)*64 + t] = acc;
    }
  }
}

// ---------------- launch ----------------
extern "C" void kernel_launch(void* const* d_in, const int* in_sizes, int n_in,
                              void* d_out, int out_size){
  (void)in_sizes; (void)n_in; (void)out_size;
  const float* t1 = (const float*)d_in[0];
  const float* t2 = (const float*)d_in[1];
  const float* t3 = (const float*)d_in[2];
  const float* t4 = (const float*)d_in[3];
  const float* t5 = (const float*)d_in[4];
  float* out = (float*)d_out;

  k1_gather<<<BTOK/256, 256>>>(t1,t2,t3,t4,t5,(const float*)d_in[5]);
  k3_scanA<<<NB*TOTC, 256>>>((const float*)d_in[8],(const float*)d_in[6],
                             (const float*)d_in[7],(const float*)d_in[9],
                             (const float*)d_in[10],(const float*)d_in[11]);
  k4_chunk<<<32, 256>>>();
  k5_scanC<<<NB*TOTC, 256>>>((const float*)d_in[8],(const float*)d_in[6],
                             (const float*)d_in[7],(const float*)d_in[9],
                             (const float*)d_in[10],(const float*)d_in[11],
                             (const float*)d_in[13],(const float*)d_in[12],
                             (const float*)d_in[23],(const float*)d_in[24],
                             (const float*)d_in[25],(const float*)d_in[26],
                             (const float*)d_in[31], out);
  k6_m1   <<<NB, 512>>>(t5,(const float*)d_in[14],(const float*)d_in[15],
                        (const float*)d_in[16],(const float*)d_in[17],
                        (const float*)d_in[18],(const float*)d_in[19],
                        (const float*)d_in[20],(const float*)d_in[21],
                        (const float*)d_in[22],(const float*)d_in[27],
                        (const float*)d_in[28],(const float*)d_in[29],
                        (const float*)d_in[30],(const float*)d_in[31], out);
}

// round 8
// speedup vs baseline: 1.6637x; 1.1022x over previous
#include <cuda_runtime.h>
#include <math.h>

// ---------------- problem geometry ----------------
#define LTOT 28928          // tokens per batch across seqs 0..3
#define BTOK 231424         // 8 * LTOT
#define TOTC 452            // chunks (T=64) per batch: 341+85+21+5
#define NB   8

// ---------------- static device scratch ----------------
__device__ float g_x8[8][BTOK];     // gathered dm=8 input tokens (channel-major)
__device__ float g_xz[32][BTOK];    // in-proj output: xi (0..15), z (16..31)
__device__ float g_P[NB*TOTC*256];  // per-chunk product of a
__device__ float g_S[NB*TOTC*256];  // per-chunk local scan end (h_start=0)
__device__ float g_H[NB*TOTC*256];  // h_start per chunk

__constant__ int c_plen[5]  = {16384,4096,1024,256,64};      // spatial size per tensor (= ch stride)
__constant__ int c_bs[5]    = {131072,65536,24576,8192,3072};// batch stride per tensor
__constant__ int c_obase[5] = {0,1048576,1572864,1769472,1835008};
__constant__ int c_O[4]     = {0,21824,27264,28608};         // seq offsets within a batch
__constant__ int c_CB[4]    = {0,341,426,447};               // chunk base per seq
__constant__ int c_NC[4]    = {341,85,21,5};                 // chunks per seq

__device__ __forceinline__ float siluf(float x){ return x * (1.0f/(1.0f+__expf(-x))); }
__device__ __forceinline__ float softplusf(float x){ return (x>20.0f)? x : log1pf(__expf(x)); }

// ---------------- K1: gather + in-projection ----------------
__global__ void k1_gather(const float* __restrict__ t1, const float* __restrict__ t2,
                          const float* __restrict__ t3, const float* __restrict__ t4,
                          const float* __restrict__ t5, const float* __restrict__ in_w){
  __shared__ float s_w[256]; // (32,8)
  int tid = threadIdx.x;
  if (tid < 256) s_w[tid] = in_w[tid];
  __syncthreads();
  int tg = blockIdx.x*256 + tid;           // < BTOK exactly (904 blocks)
  int b = tg / LTOT, r = tg % LTOT;
  int s = (r>=21824)+(r>=27264)+(r>=28608);
  int p = r - c_O[s];
  int i = s, pp = p;
  while (pp >= c_plen[i]) { pp -= c_plen[i]; ++i; }
  const float* tp = (i==0)?t1:(i==1)?t2:(i==2)?t3:(i==3)?t4:t5;
  int base = b*c_bs[i] + (8*s)*c_plen[i] + pp;
  float x[8];
  #pragma unroll
  for (int c=0;c<8;c++){ x[c] = tp[base + c*c_plen[i]]; g_x8[c][tg] = x[c]; }
  #pragma unroll
  for (int j=0;j<32;j++){
    float v = 0.f;
    #pragma unroll
    for (int c=0;c<8;c++) v += x[c]*s_w[j*8+c];
    g_xz[j][tg] = v;
  }
}

// ======= shared record-recompute used by fused scan kernels ===============
// xi[d][j]: token tb-4+j (conv taps j=t+1..t+4)
// xcs[d][t]: conv+silu output
// dldu[d][t] = {delta, delta*xc}   (broadcast reads in scan)
// BC[n][t]   = {B, C}              (stride 65 float2 -> conflict-free over n)
struct RecSmem {
  float  xi[16][68];
  float  xcs[16][66];
  float2 dldu[16][65];
  float2 BC[16][65];
  float  dtv[64];
  float  xp[33*16];
  float  cw[64], cb[16], dtw[16], dtb[16];
};

template<bool WANTC>
__device__ __forceinline__ void rec_compute(RecSmem& S, int tid, int tb, int cis,
    const float* __restrict__ xproj_w, const float* __restrict__ conv_w,
    const float* __restrict__ conv_b,  const float* __restrict__ dt_w,
    const float* __restrict__ dt_b){
  // params
  for (int i=tid;i<528;i+=256) S.xp[i]=xproj_w[i];
  if (tid<64) S.cw[tid]=conv_w[tid];
  if (tid<16){ S.cb[tid]=conv_b[tid]; S.dtw[tid]=dt_w[tid]; S.dtb[tid]=dt_b[tid]; }
  // xi halo load: 16 rows x 17 float4 (tokens tb-4 .. tb+63)
  for (int i=tid;i<272;i+=256){
    int d=i/17, q=i%17;
    float4 v;
    if (cis==0 && q==0) v = make_float4(0.f,0.f,0.f,0.f);
    else v = *reinterpret_cast<const float4*>(&g_xz[d][tb-4+q*4]);
    S.xi[d][q*4+0]=v.x; S.xi[d][q*4+1]=v.y; S.xi[d][q*4+2]=v.z; S.xi[d][q*4+3]=v.w;
  }
  __syncthreads();
  // conv + silu -> xcs
  #pragma unroll
  for (int k=0;k<4;k++){
    int idx = tid + k*256;
    int d = idx>>6, t = idx&63;
    float acc = S.cb[d];
    #pragma unroll
    for (int kk=0;kk<4;kk++) acc += S.cw[d*4+kk]*S.xi[d][t+1+kk];
    S.xcs[d][t] = siluf(acc);
  }
  __syncthreads();
  // dt row
  if (tid<64){
    float v=0.f;
    #pragma unroll
    for (int d=0;d<16;d++) v += S.xcs[d][tid]*S.xp[d];
    S.dtv[tid]=v;
  }
  __syncthreads();
  // B and C together -> packed float2
  #pragma unroll
  for (int k=0;k<4;k++){
    int idx = tid + k*256;          // 0..1023
    int t = idx&63, j = idx>>6;     // j 0..15
    float bv=0.f, cv=0.f;
    #pragma unroll
    for (int d=0;d<16;d++){
      float xc = S.xcs[d][t];
      bv += xc*S.xp[(1+j)*16+d];
      if (WANTC) cv += xc*S.xp[(17+j)*16+d];
    }
    S.BC[j][t] = make_float2(bv, cv);
  }
  // delta + delta*xc -> packed float2
  #pragma unroll
  for (int k=0;k<4;k++){
    int idx = tid + k*256;
    int d = idx>>6, t = idx&63;
    float del = softplusf(S.dtv[t]*S.dtw[d]+S.dtb[d]);
    S.dldu[d][t] = make_float2(del, del*S.xcs[d][t]);
  }
  __syncthreads();
}

// ---------------- K3: fused record recompute + phase A (P,S) --------------
__global__ void k3_scanA(const float* __restrict__ xproj_w, const float* __restrict__ conv_w,
                         const float* __restrict__ conv_b, const float* __restrict__ dt_w,
                         const float* __restrict__ dt_b, const float* __restrict__ Alog){
  __shared__ RecSmem S;
  int blk = blockIdx.x;
  int b = blk / TOTC, cg = blk % TOTC;
  int s = (cg>=341)+(cg>=426)+(cg>=447);
  int cis = cg - c_CB[s];
  int tb = b*LTOT + c_O[s] + cis*64;
  int tid = threadIdx.x;
  float ac = -__expf(Alog[tid])*1.4426950408889634f;
  rec_compute<false>(S, tid, tb, cis, xproj_w, conv_w, conv_b, dt_w, dt_b);
  int d = tid>>4, n = tid&15;
  float h=0.f, P=1.f;
  #pragma unroll 8
  for (int t=0;t<64;t++){
    float2 v = S.dldu[d][t];
    float a = exp2f(v.x*ac);
    h = a*h + v.y*S.BC[n][t].x;
    P *= a;
  }
  int idx = (b*TOTC+cg)*256+tid;
  g_P[idx]=P; g_S[idx]=h;
}

// ---------------- K4: chunk-prefix scan, software-pipelined ----------------
__global__ void k4_chunk(){
  constexpr int U = 16;
  int b = blockIdx.x >> 2, s = blockIdx.x & 3;
  int tid = threadIdx.x;
  int base = (b*TOTC + c_CB[s])*256 + tid;
  int nc = c_NC[s];
  int nbatch = (nc + U - 1)/U;
  float PA[U],SA[U],PB[U],SB[U];
  #pragma unroll
  for (int u=0;u<U;u++){
    if (u<nc){ int idx=base+u*256; PA[u]=g_P[idx]; SA[u]=g_S[idx]; }
    else { PA[u]=1.f; SA[u]=0.f; }
  }
  float H=0.f;
  for (int bi=0; bi<nbatch; bi+=2){
    if (bi+1<nbatch){
      #pragma unroll
      for (int u=0;u<U;u++){
        int c=(bi+1)*U+u;
        if (c<nc){ int idx=base+c*256; PB[u]=g_P[idx]; SB[u]=g_S[idx]; }
        else { PB[u]=1.f; SB[u]=0.f; }
      }
    }
    #pragma unroll
    for (int u=0;u<U;u++){
      int c=bi*U+u;
      if (c<nc){ g_H[base+c*256]=H; H = PA[u]*H + SA[u]; }
    }
    if (bi+2<nbatch){
      #pragma unroll
      for (int u=0;u<U;u++){
        int c=(bi+2)*U+u;
        if (c<nc){ int idx=base+c*256; PA[u]=g_P[idx]; SA[u]=g_S[idx]; }
        else { PA[u]=1.f; SA[u]=0.f; }
      }
    }
    if (bi+1<nbatch){
      #pragma unroll
      for (int u=0;u<U;u++){
        int c=(bi+1)*U+u;
        if (c<nc){ g_H[base+c*256]=H; H = PB[u]*H + SB[u]; }
      }
    }
  }
}

// ---------------- K5: fused recompute + phase C + epilogue + scatter -------
struct K5Smem {
  RecSmem R;
  float y2[16][2][66];   // two reduction partials per (d,t), transposed for epilogue
  float zsh[16][66];
  float x8sh[8][66];
  float ow[128], pwm[64], pbv[8], gv[8], nbvv[8], Dvv[16];
  float skip;
};

__global__ void k5_scanC(const float* __restrict__ xproj_w, const float* __restrict__ conv_w,
                         const float* __restrict__ conv_b, const float* __restrict__ dt_w,
                         const float* __restrict__ dt_b, const float* __restrict__ Alog,
                         const float* __restrict__ out_w, const float* __restrict__ Dv,
                         const float* __restrict__ ng, const float* __restrict__ nbv,
                         const float* __restrict__ pw, const float* __restrict__ pb,
                         const float* __restrict__ skipp, float* __restrict__ out){
  __shared__ K5Smem S;
  int blk = blockIdx.x;
  int b = blk / TOTC, cg = blk % TOTC;
  int s = (cg>=341)+(cg>=426)+(cg>=447);
  int cis = cg - c_CB[s];
  int tb = b*LTOT + c_O[s] + cis*64;
  int tid = threadIdx.x;
  float ac = -__expf(Alog[tid])*1.4426950408889634f;
  float h = g_H[(b*TOTC+cg)*256+tid];
  // epilogue params + z/x8 staging (disjoint smem; synced by rec_compute's barriers)
  {
    int d4=tid>>4, q4=tid&15;  // z staging
    float4 v = *reinterpret_cast<const float4*>(&g_xz[16+d4][tb+q4*4]);
    S.zsh[d4][q4*4+0]=v.x; S.zsh[d4][q4*4+1]=v.y; S.zsh[d4][q4*4+2]=v.z; S.zsh[d4][q4*4+3]=v.w;
    if (tid<128){
      int d8=tid>>4, q8=tid&15;
      float4 w = *reinterpret_cast<const float4*>(&g_x8[d8][tb+q8*4]);
      S.x8sh[d8][q8*4+0]=w.x; S.x8sh[d8][q8*4+1]=w.y; S.x8sh[d8][q8*4+2]=w.z; S.x8sh[d8][q8*4+3]=w.w;
    } else {
      int u = tid-128;
      if (u<128) S.ow[u]=out_w[u];
    }
    if (tid<64) S.pwm[tid]=pw[tid];
    else if (tid<72) S.pbv[tid-64]=pb[tid-64];
    else if (tid<80) S.gv[tid-72]=ng[tid-72];
    else if (tid<88) S.nbvv[tid-80]=nbv[tid-80];
    else if (tid<104) S.Dvv[tid-88]=Dv[tid-88];
    else if (tid==104) S.skip = skipp[0];
  }
  rec_compute<true>(S.R, tid, tb, cis, xproj_w, conv_w, conv_b, dt_w, dt_b);
  int d=tid>>4, n=tid&15;
  #pragma unroll 8
  for (int t=0;t<64;t++){
    float2 v = S.R.dldu[d][t];
    float a = exp2f(v.x*ac);
    float2 bc = S.R.BC[n][t];
    h = a*h + v.y*bc.x;
    float pr = h*bc.y;
    pr += __shfl_xor_sync(0xffffffffu, pr, 8);
    pr += __shfl_xor_sync(0xffffffffu, pr, 4);
    pr += __shfl_xor_sync(0xffffffffu, pr, 2);
    if (n<2) S.y2[d][n][t]=pr;
  }
  __syncthreads();
  if (tid < 64){
    int t = tid;
    float yf[16];
    #pragma unroll
    for (int dd=0;dd<16;dd++){
      float z = S.zsh[dd][t];
      float ysum = S.y2[dd][0][t] + S.y2[dd][1][t];
      yf[dd] = (ysum + S.R.xcs[dd][t]*S.Dvv[dd]) * siluf(z);
    }
    float o[8]; float mu=0.f;
    #pragma unroll
    for (int ch=0;ch<8;ch++){
      float acc = S.skip * S.x8sh[ch][t];
      #pragma unroll
      for (int dd=0;dd<16;dd++) acc += yf[dd]*S.ow[ch*16+dd];
      o[ch]=acc; mu+=acc;
    }
    mu *= 0.125f;
    float var=0.f;
    #pragma unroll
    for (int ch=0;ch<8;ch++){ float dv=o[ch]-mu; var += dv*dv; }
    var *= 0.125f;
    float rs = rsqrtf(var + 1e-5f);
    float ln[8];
    #pragma unroll
    for (int ch=0;ch<8;ch++) ln[ch] = (o[ch]-mu)*rs*S.gv[ch] + S.nbvv[ch];
    // scatter
    int p = cis*64 + t;
    int i = s, pp = p;
    while (pp >= c_plen[i]) { pp -= c_plen[i]; ++i; }
    int base = c_obase[i] + b*c_bs[i] + (8*s)*c_plen[i] + pp;
    #pragma unroll
    for (int j=0;j<8;j++){
      float acc = S.pbv[j];
      #pragma unroll
      for (int ch=0;ch<8;ch++) acc += ln[ch]*S.pwm[j*8+ch];
      out[base + j*c_plen[i]] = acc;
    }
  }
}

// ---------------- K6: whole m1 path (c5, L=64, dm=16) in one kernel ----------------
__global__ void k6_m1(const float* __restrict__ t5, const float* __restrict__ in_w,
                      const float* __restrict__ conv_w, const float* __restrict__ conv_b,
                      const float* __restrict__ xproj_w, const float* __restrict__ dt_w,
                      const float* __restrict__ dt_b, const float* __restrict__ Alog,
                      const float* __restrict__ Dv, const float* __restrict__ out_w,
                      const float* __restrict__ ng, const float* __restrict__ nbv,
                      const float* __restrict__ pw, const float* __restrict__ pb,
                      const float* __restrict__ skipp, float* __restrict__ out){
  __shared__ float s_x[64][16];
  __shared__ float s_xi[64][32];   // reused as delta after conv
  __shared__ float s_z[64][32];
  __shared__ float s_xc[64][32];
  __shared__ float s_B[64][16];
  __shared__ float s_C[64][16];
  __shared__ float s_dt[64];
  __shared__ float s_y[64][32];
  int b = blockIdx.x, tid = threadIdx.x;
  for (int i=tid;i<64*16;i+=512){
    int t=i>>4, c=i&15;
    s_x[t][c] = t5[b*3072 + (32+c)*64 + t];
  }
  __syncthreads();
  for (int i=tid;i<64*64;i+=512){     // in-proj
    int t=i>>6, j=i&63;
    float v=0.f;
    #pragma unroll
    for (int c=0;c<16;c++) v += s_x[t][c]*in_w[j*16+c];
    if (j<32) s_xi[t][j]=v; else s_z[t][j-32]=v;
  }
  __syncthreads();
  for (int i=tid;i<64*32;i+=512){     // conv + silu
    int t=i>>5, d=i&31;
    float acc = conv_b[d];
    #pragma unroll
    for (int k=0;k<4;k++){
      int tt = t-3+k;
      if (tt>=0) acc += conv_w[d*4+k]*s_xi[tt][d];
    }
    s_xc[t][d] = siluf(acc);
  }
  __syncthreads();
  for (int i=tid;i<64*33;i+=512){     // x-proj
    int t=i/33, j=i%33;
    float v=0.f;
    #pragma unroll
    for (int d=0;d<32;d++) v += s_xc[t][d]*xproj_w[j*32+d];
    if (j==0) s_dt[t]=v;
    else if (j<17) s_B[t][j-1]=v;
    else s_C[t][j-17]=v;
  }
  __syncthreads();
  for (int i=tid;i<64*32;i+=512){     // delta (overwrites s_xi)
    int t=i>>5, d=i&31;
    s_xi[t][d] = softplusf(s_dt[t]*dt_w[d] + dt_b[d]);
  }
  __syncthreads();
  {                                    // scan: thread = (d,n), 32*16 = 512 lanes
    int d=tid>>4, n=tid&15;
    float ac = -__expf(Alog[d*16+n])*1.4426950408889634f;
    float h=0.f;
    for (int t=0;t<64;t++){
      float dl = s_xi[t][d];
      float a = exp2f(dl*ac);
      h = a*h + dl*s_xc[t][d]*s_B[t][n];
      float pr = h*s_C[t][n];
      pr += __shfl_xor_sync(0xffffffffu, pr, 8);
      pr += __shfl_xor_sync(0xffffffffu, pr, 4);
      pr += __shfl_xor_sync(0xffffffffu, pr, 2);
      pr += __shfl_xor_sync(0xffffffffu, pr, 1);
      if (n==0) s_y[t][d]=pr;
    }
  }
  __syncthreads();
  if (tid<64){
    int t=tid;
    float skip = skipp[0];
    float yf[32];
    #pragma unroll
    for (int d=0;d<32;d++) yf[d] = (s_y[t][d] + s_xc[t][d]*Dv[d]) * siluf(s_z[t][d]);
    float o[16]; float mu=0.f;
    #pragma unroll
    for (int ch=0;ch<16;ch++){
      float acc = skip * s_x[t][ch];
      #pragma unroll
      for (int d=0;d<32;d++) acc += yf[d]*out_w[ch*32+d];
      o[ch]=acc; mu+=acc;
    }
    mu *= (1.0f/16.0f);
    float var=0.f;
    #pragma unroll
    for (int ch=0;ch<16;ch++){ float dv=o[ch]-mu; var+=dv*dv; }
    var *= (1.0f/16.0f);
    float rs = rsqrtf(var+1e-5f);
    float ln[16];
    #pragma unroll
    for (int ch=0;ch<16;ch++) ln[ch] = (o[ch]-mu)*rs*ng[ch]+nbv[ch];
    #pragma unroll
    for (int j=0;j<16;j++){
      float acc = pb[j];
      #pragma unroll
      for (int ch=0;ch<16;ch++) acc += ln[ch]*pw[j*16+ch];
      out[1835008 + b*3072 + (32+j)*64 + t] = acc;
    }
  }
}

// ---------------- launch ----------------
extern "C" void kernel_launch(void* const* d_in, const int* in_sizes, int n_in,
                              void* d_out, int out_size){
  (void)in_sizes; (void)n_in; (void)out_size;
  const float* t1 = (const float*)d_in[0];
  const float* t2 = (const float*)d_in[1];
  const float* t3 = (const float*)d_in[2];
  const float* t4 = (const float*)d_in[3];
  const float* t5 = (const float*)d_in[4];
  float* out = (float*)d_out;

  k1_gather<<<BTOK/256, 256>>>(t1,t2,t3,t4,t5,(const float*)d_in[5]);
  k3_scanA<<<NB*TOTC, 256>>>((const float*)d_in[8],(const float*)d_in[6],
                             (const float*)d_in[7],(const float*)d_in[9],
                             (const float*)d_in[10],(const float*)d_in[11]);
  k4_chunk<<<32, 256>>>();
  k5_scanC<<<NB*TOTC, 256>>>((const float*)d_in[8],(const float*)d_in[6],
                             (const float*)d_in[7],(const float*)d_in[9],
                             (const float*)d_in[10],(const float*)d_in[11],
                             (const float*)d_in[13],(const float*)d_in[12],
                             (const float*)d_in[23],(const float*)d_in[24],
                             (const float*)d_in[25],(const float*)d_in[26],
                             (const float*)d_in[31], out);
  k6_m1   <<<NB, 512>>>(t5,(const float*)d_in[14],(const float*)d_in[15],
                        (const float*)d_in[16],(const float*)d_in[17],
                        (const float*)d_in[18],(const float*)d_in[19],
                        (const float*)d_in[20],(const float*)d_in[21],
                        (const float*)d_in[22],(const float*)d_in[27],
                        (const float*)d_in[28],(const float*)d_in[29],
                        (const float*)d_in[30],(const float*)d_in[31], out);
}

// round 10
// speedup vs baseline: 1.6928x; 1.0175x over previous
#include <cuda_runtime.h>
#include <math.h>

// ---------------- problem geometry ----------------
#define LTOT 28928          // tokens per batch across seqs 0..3
#define BTOK 231424         // 8 * LTOT
#define TOTC 452            // chunks (T=64) per batch: 341+85+21+5
#define NB   8

// ---------------- static device scratch ----------------
__device__ __align__(16) float g_xz[32][BTOK]; // in-proj output: xi (0..15), z (16..31)
__device__ __align__(16) float g_P[NB*TOTC*256];  // per-chunk product of a
__device__ __align__(16) float g_S[NB*TOTC*256];  // per-chunk local scan end
__device__ __align__(16) float g_H[NB*TOTC*256];  // h_start per chunk

__constant__ int c_plen[5]  = {16384,4096,1024,256,64};      // spatial size per tensor (= ch stride)
__constant__ int c_bs[5]    = {131072,65536,24576,8192,3072};// batch stride per tensor
__constant__ int c_obase[5] = {0,1048576,1572864,1769472,1835008};
__constant__ int c_O[4]     = {0,21824,27264,28608};         // seq offsets within a batch
__constant__ int c_CB[4]    = {0,341,426,447};               // chunk base per seq
__constant__ int c_NC[4]    = {341,85,21,5};                 // chunks per seq

__device__ __forceinline__ float siluf(float x){ return x * (1.0f/(1.0f+__expf(-x))); }
__device__ __forceinline__ float softplusf(float x){ return (x>20.0f)? x : log1pf(__expf(x)); }

// ---------------- K1: gather + in-projection ----------------
__global__ void k1_gather(const float* __restrict__ t1, const float* __restrict__ t2,
                          const float* __restrict__ t3, const float* __restrict__ t4,
                          const float* __restrict__ t5, const float* __restrict__ in_w){
  __shared__ float s_w[256]; // (32,8)
  int tid = threadIdx.x;
  if (tid < 256) s_w[tid] = in_w[tid];
  __syncthreads();
  int tg = blockIdx.x*256 + tid;           // < BTOK exactly (904 blocks)
  int b = tg / LTOT, r = tg % LTOT;
  int s = (r>=21824)+(r>=27264)+(r>=28608);
  int p = r - c_O[s];
  int i = s, pp = p;
  while (pp >= c_plen[i]) { pp -= c_plen[i]; ++i; }
  const float* tp = (i==0)?t1:(i==1)?t2:(i==2)?t3:(i==3)?t4:t5;
  int base = b*c_bs[i] + (8*s)*c_plen[i] + pp;
  float x[8];
  #pragma unroll
  for (int c=0;c<8;c++) x[c] = tp[base + c*c_plen[i]];
  #pragma unroll
  for (int j=0;j<32;j++){
    float v = 0.f;
    #pragma unroll
    for (int c=0;c<8;c++) v += x[c]*s_w[j*8+c];
    g_xz[j][tg] = v;
  }
}

// ======= shared record-recompute used by fused scan kernels ===============
// alignas(16): every float4-accessed member sits at a 16B-aligned offset.
// xi@0, xcs@4352, dldu@8704, BC@17024, dtv@25600, xp@25856 (564 fl = 2256B),
// cw@28112? -> recomputed: xp 2256 -> 28112, cw 256 -> 28368... (offsets all
// checked to keep sizeof(RecSmem) % 16 == 0)
struct alignas(16) RecSmem {
  float  xi[16][68];      // 4352 B, float4-stored
  float  xcs[16][68];     // 4352 B, float4-read
  float2 dldu[16][65];    // 8320 B
  float2 BC[16][65];      // 8320 B
  float  dtv[64];         // 256 B
  float  xp[564];         // 33*17=561, padded to 564 (2256 B)
  float  cw[64], cb[16], dtw[16], dtb[16];
  float  pad[4];          // keep sizeof % 16 == 0
};

template<bool WANTC>
__device__ __forceinline__ void rec_compute(RecSmem& S, int tid, int tb, int cis,
    const float* __restrict__ xproj_w, const float* __restrict__ conv_w,
    const float* __restrict__ conv_b,  const float* __restrict__ dt_w,
    const float* __restrict__ dt_b){
  // params (xp padded to stride 17)
  for (int i=tid;i<528;i+=256){ int row=i>>4, col=i&15; S.xp[row*17+col]=xproj_w[i]; }
  if (tid<64) S.cw[tid]=conv_w[tid];
  if (tid<16){ S.cb[tid]=conv_b[tid]; S.dtw[tid]=dt_w[tid]; S.dtb[tid]=dt_b[tid]; }
  // xi halo load: 16 rows x 17 float4 (tokens tb-4 .. tb+63)
  for (int i=tid;i<272;i+=256){
    int d=i/17, q=i%17;
    float4 v;
    if (cis==0 && q==0) v = make_float4(0.f,0.f,0.f,0.f);
    else v = *reinterpret_cast<const float4*>(&g_xz[d][tb-4+q*4]);
    S.xi[d][q*4+0]=v.x; S.xi[d][q*4+1]=v.y; S.xi[d][q*4+2]=v.z; S.xi[d][q*4+3]=v.w;
  }
  __syncthreads();
  // conv + silu -> xcs
  #pragma unroll
  for (int k=0;k<4;k++){
    int idx = tid + k*256;
    int d = idx>>6, t = idx&63;
    float acc = S.cb[d];
    #pragma unroll
    for (int kk=0;kk<4;kk++) acc += S.cw[d*4+kk]*S.xi[d][t+1+kk];
    S.xcs[d][t] = siluf(acc);
  }
  __syncthreads();
  // dt row (xp row 0)
  if (tid<64){
    float v=0.f;
    #pragma unroll
    for (int d=0;d<16;d++) v += S.xcs[d][tid]*S.xp[d];
    S.dtv[tid]=v;
  }
  __syncthreads();
  // B and C dots, t-blocked: thread = (j, t-group of 4); xcs read via float4
  {
    int j = tid & 15;
    int t0 = (tid >> 4) << 2;
    float aB0=0.f,aB1=0.f,aB2=0.f,aB3=0.f;
    float aC0=0.f,aC1=0.f,aC2=0.f,aC3=0.f;
    #pragma unroll
    for (int d=0;d<16;d++){
      float4 x4 = *reinterpret_cast<const float4*>(&S.xcs[d][t0]);
      float wb = S.xp[(1+j)*17+d];
      aB0 += x4.x*wb; aB1 += x4.y*wb; aB2 += x4.z*wb; aB3 += x4.w*wb;
      if (WANTC){
        float wc = S.xp[(17+j)*17+d];
        aC0 += x4.x*wc; aC1 += x4.y*wc; aC2 += x4.z*wc; aC3 += x4.w*wc;
      }
    }
    S.BC[j][t0+0] = make_float2(aB0, aC0);
    S.BC[j][t0+1] = make_float2(aB1, aC1);
    S.BC[j][t0+2] = make_float2(aB2, aC2);
    S.BC[j][t0+3] = make_float2(aB3, aC3);
  }
  // delta + delta*xc
  #pragma unroll
  for (int k=0;k<4;k++){
    int idx = tid + k*256;
    int d = idx>>6, t = idx&63;
    float del = softplusf(S.dtv[t]*S.dtw[d]+S.dtb[d]);
    S.dldu[d][t] = make_float2(del, del*S.xcs[d][t]);
  }
  __syncthreads();
}

// ---------------- K3: fused record recompute + phase A (P,S) --------------
// scan: 64 threads, thread=(d,ng), h[4]/P[4] in registers
__global__ void k3_scanA(const float* __restrict__ xproj_w, const float* __restrict__ conv_w,
                         const float* __restrict__ conv_b, const float* __restrict__ dt_w,
                         const float* __restrict__ dt_b, const float* __restrict__ Alog){
  __shared__ RecSmem S;
  int blk = blockIdx.x;
  int b = blk / TOTC, cg = blk % TOTC;
  int s = (cg>=341)+(cg>=426)+(cg>=447);
  int cis = cg - c_CB[s];
  int tb = b*LTOT + c_O[s] + cis*64;
  int tid = threadIdx.x;
  rec_compute<false>(S, tid, tb, cis, xproj_w, conv_w, conv_b, dt_w, dt_b);
  if (tid < 64){
    int d = tid>>2, ng = tid&3;
    float4 al = *reinterpret_cast<const float4*>(&Alog[d*16 + 4*ng]);
    const float L2E = 1.4426950408889634f;
    float ac0=-__expf(al.x)*L2E, ac1=-__expf(al.y)*L2E,
          ac2=-__expf(al.z)*L2E, ac3=-__expf(al.w)*L2E;
    float h0=0.f,h1=0.f,h2=0.f,h3=0.f;
    float P0=1.f,P1=1.f,P2=1.f,P3=1.f;
    #pragma unroll 4
    for (int t=0;t<64;t++){
      float2 du = S.dldu[d][t];
      float b0 = S.BC[4*ng+0][t].x;
      float b1 = S.BC[4*ng+1][t].x;
      float b2 = S.BC[4*ng+2][t].x;
      float b3 = S.BC[4*ng+3][t].x;
      float a0=exp2f(du.x*ac0), a1=exp2f(du.x*ac1),
            a2=exp2f(du.x*ac2), a3=exp2f(du.x*ac3);
      h0 = a0*h0 + du.y*b0;  P0 *= a0;
      h1 = a1*h1 + du.y*b1;  P1 *= a1;
      h2 = a2*h2 + du.y*b2;  P2 *= a2;
      h3 = a3*h3 + du.y*b3;  P3 *= a3;
    }
    int idx = (b*TOTC+cg)*256 + d*16 + 4*ng;
    *reinterpret_cast<float4*>(&g_P[idx]) = make_float4(P0,P1,P2,P3);
    *reinterpret_cast<float4*>(&g_S[idx]) = make_float4(h0,h1,h2,h3);
  }
}

// ---------------- K4: chunk-prefix scan, software-pipelined ----------------
__global__ void k4_chunk(){
  constexpr int U = 16;
  int b = blockIdx.x >> 2, s = blockIdx.x & 3;
  int tid = threadIdx.x;
  int base = (b*TOTC + c_CB[s])*256 + tid;
  int nc = c_NC[s];
  int nbatch = (nc + U - 1)/U;
  float PA[U],SA[U],PB[U],SB[U];
  #pragma unroll
  for (int u=0;u<U;u++){
    if (u<nc){ int idx=base+u*256; PA[u]=g_P[idx]; SA[u]=g_S[idx]; }
    else { PA[u]=1.f; SA[u]=0.f; }
  }
  float H=0.f;
  for (int bi=0; bi<nbatch; bi+=2){
    if (bi+1<nbatch){
      #pragma unroll
      for (int u=0;u<U;u++){
        int c=(bi+1)*U+u;
        if (c<nc){ int idx=base+c*256; PB[u]=g_P[idx]; SB[u]=g_S[idx]; }
        else { PB[u]=1.f; SB[u]=0.f; }
      }
    }
    #pragma unroll
    for (int u=0;u<U;u++){
      int c=bi*U+u;
      if (c<nc){ g_H[base+c*256]=H; H = PA[u]*H + SA[u]; }
    }
    if (bi+2<nbatch){
      #pragma unroll
      for (int u=0;u<U;u++){
        int c=(bi+2)*U+u;
        if (c<nc){ int idx=base+c*256; PA[u]=g_P[idx]; SA[u]=g_S[idx]; }
        else { PA[u]=1.f; SA[u]=0.f; }
      }
    }
    if (bi+1<nbatch){
      #pragma unroll
      for (int u=0;u<U;u++){
        int c=(bi+1)*U+u;
        if (c<nc){ g_H[base+c*256]=H; H = PB[u]*H + SB[u]; }
      }
    }
  }
}

// ---------------- K5: fused recompute + phase C + epilogue + scatter -------
struct alignas(16) K5Smem {
  RecSmem R;             // sizeof % 16 == 0, so members below stay 16B-aligned
  float y[16][68];       // fully reduced y per (d,t)
  float zsh[16][68];     // float4-stored
  float x8sh[8][68];     // float4-stored
  float ow[128], pwm[64], pbv[8], gv[8], nbvv[8], Dvv[16];
  float skip;
};

__global__ void k5_scanC(const float* __restrict__ t1, const float* __restrict__ t2,
                         const float* __restrict__ t3, const float* __restrict__ t4,
                         const float* __restrict__ t5,
                         const float* __restrict__ xproj_w, const float* __restrict__ conv_w,
                         const float* __restrict__ conv_b, const float* __restrict__ dt_w,
                         const float* __restrict__ dt_b, const float* __restrict__ Alog,
                         const float* __restrict__ out_w, const float* __restrict__ Dv,
                         const float* __restrict__ ng_, const float* __restrict__ nbv,
                         const float* __restrict__ pw, const float* __restrict__ pb,
                         const float* __restrict__ skipp, float* __restrict__ out){
  __shared__ K5Smem S;
  int blk = blockIdx.x;
  int b = blk / TOTC, cg = blk % TOTC;
  int s = (cg>=341)+(cg>=426)+(cg>=447);
  int cis = cg - c_CB[s];
  int tb = b*LTOT + c_O[s] + cis*64;
  int tid = threadIdx.x;
  // block-uniform tensor mapping (chunk lies entirely inside one tensor)
  int ti = s, pp = cis*64;
  while (pp >= c_plen[ti]) { pp -= c_plen[ti]; ++ti; }
  const float* tp = (ti==0)?t1:(ti==1)?t2:(ti==2)?t3:(ti==3)?t4:t5;
  int ibase = b*c_bs[ti] + (8*s)*c_plen[ti] + pp;
  // staging: z, x8 (from input), epilogue params (disjoint smem; rec_compute barriers order it)
  {
    int d4=tid>>4, q4=tid&15;  // z staging: 16 ch x 16 float4
    float4 v = *reinterpret_cast<const float4*>(&g_xz[16+d4][tb+q4*4]);
    *reinterpret_cast<float4*>(&S.zsh[d4][q4*4]) = v;
    if (tid<128){
      int d8=tid>>4, q8=tid&15;
      float4 w = *reinterpret_cast<const float4*>(&tp[ibase + d8*c_plen[ti] + q8*4]);
      *reinterpret_cast<float4*>(&S.x8sh[d8][q8*4]) = w;
    } else {
      int u = tid-128;
      if (u<128) S.ow[u]=out_w[u];
    }
    if (tid<64) S.pwm[tid]=pw[tid];
    else if (tid<72) S.pbv[tid-64]=pb[tid-64];
    else if (tid<80) S.gv[tid-72]=ng_[tid-72];
    else if (tid<88) S.nbvv[tid-80]=nbv[tid-80];
    else if (tid<104) S.Dvv[tid-88]=Dv[tid-88];
    else if (tid==104) S.skip = skipp[0];
  }
  rec_compute<true>(S.R, tid, tb, cis, xproj_w, conv_w, conv_b, dt_w, dt_b);
  if (tid < 64){
    int d = tid>>2, ngi = tid&3;
    float4 al = *reinterpret_cast<const float4*>(&Alog[d*16 + 4*ngi]);
    const float L2E = 1.4426950408889634f;
    float ac0=-__expf(al.x)*L2E, ac1=-__expf(al.y)*L2E,
          ac2=-__expf(al.z)*L2E, ac3=-__expf(al.w)*L2E;
    int hidx = (b*TOTC+cg)*256 + d*16 + 4*ngi;
    float4 h4 = *reinterpret_cast<const float4*>(&g_H[hidx]);
    float h0=h4.x,h1=h4.y,h2=h4.z,h3=h4.w;
    #pragma unroll 4
    for (int t=0;t<64;t++){
      float2 du = S.R.dldu[d][t];
      float2 bc0 = S.R.BC[4*ngi+0][t];
      float2 bc1 = S.R.BC[4*ngi+1][t];
      float2 bc2 = S.R.BC[4*ngi+2][t];
      float2 bc3 = S.R.BC[4*ngi+3][t];
      float a0=exp2f(du.x*ac0), a1=exp2f(du.x*ac1),
            a2=exp2f(du.x*ac2), a3=exp2f(du.x*ac3);
      h0 = a0*h0 + du.y*bc0.x;
      h1 = a1*h1 + du.y*bc1.x;
      h2 = a2*h2 + du.y*bc2.x;
      h3 = a3*h3 + du.y*bc3.x;
      float pr = h0*bc0.y + h1*bc1.y + h2*bc2.y + h3*bc3.y;
      pr += __shfl_xor_sync(0xffffffffu, pr, 1);
      pr += __shfl_xor_sync(0xffffffffu, pr, 2);
      if (ngi==0) S.y[d][t]=pr;
    }
  }
  __syncthreads();
  if (tid < 64){
    int t = tid;
    float yf[16];
    #pragma unroll
    for (int dd=0;dd<16;dd++){
      float z = S.zsh[dd][t];
      yf[dd] = (S.y[dd][t] + S.R.xcs[dd][t]*S.Dvv[dd]) * siluf(z);
    }
    float o[8]; float mu=0.f;
    #pragma unroll
    for (int ch=0;ch<8;ch++){
      float acc = S.skip * S.x8sh[ch][t];
      #pragma unroll
      for (int dd=0;dd<16;dd++) acc += yf[dd]*S.ow[ch*16+dd];
      o[ch]=acc; mu+=acc;
    }
    mu *= 0.125f;
    float var=0.f;
    #pragma unroll
    for (int ch=0;ch<8;ch++){ float dv=o[ch]-mu; var += dv*dv; }
    var *= 0.125f;
    float rs = rsqrtf(var + 1e-5f);
    float ln[8];
    #pragma unroll
    for (int ch=0;ch<8;ch++) ln[ch] = (o[ch]-mu)*rs*S.gv[ch] + S.nbvv[ch];
    // scatter (block-uniform tensor mapping)
    int base = c_obase[ti] + ibase + t;   // ibase == b*bs + 8s*plen + pp
    #pragma unroll
    for (int j=0;j<8;j++){
      float acc = S.pbv[j];
      #pragma unroll
      for (int ch=0;ch<8;ch++) acc += ln[ch]*S.pwm[j*8+ch];
      out[base + j*c_plen[ti]] = acc;
    }
  }
}

// ---------------- K6: whole m1 path (c5, L=64, dm=16) in one kernel ----------------
__global__ void k6_m1(const float* __restrict__ t5, const float* __restrict__ in_w,
                      const float* __restrict__ conv_w, const float* __restrict__ conv_b,
                      const float* __restrict__ xproj_w, const float* __restrict__ dt_w,
                      const float* __restrict__ dt_b, const float* __restrict__ Alog,
                      const float* __restrict__ Dv, const float* __restrict__ out_w,
                      const float* __restrict__ ng, const float* __restrict__ nbv,
                      const float* __restrict__ pw, const float* __restrict__ pb,
                      const float* __restrict__ skipp, float* __restrict__ out){
  __shared__ float s_x[64][16];
  __shared__ float s_xi[64][32];   // reused as delta after conv
  __shared__ float s_z[64][32];
  __shared__ float s_xc[64][32];
  __shared__ float s_B[64][16];
  __shared__ float s_C[64][16];
  __shared__ float s_dt[64];
  __shared__ float s_y[64][32];
  int b = blockIdx.x, tid = threadIdx.x;
  for (int i=tid;i<64*16;i+=512){
    int t=i>>4, c=i&15;
    s_x[t][c] = t5[b*3072 + (32+c)*64 + t];
  }
  __syncthreads();
  for (int i=tid;i<64*64;i+=512){     // in-proj
    int t=i>>6, j=i&63;
    float v=0.f;
    #pragma unroll
    for (int c=0;c<16;c++) v += s_x[t][c]*in_w[j*16+c];
    if (j<32) s_xi[t][j]=v; else s_z[t][j-32]=v;
  }
  __syncthreads();
  for (int i=tid;i<64*32;i+=512){     // conv + silu
    int t=i>>5, d=i&31;
    float acc = conv_b[d];
    #pragma unroll
    for (int k=0;k<4;k++){
      int tt = t-3+k;
      if (tt>=0) acc += conv_w[d*4+k]*s_xi[tt][d];
    }
    s_xc[t][d] = siluf(acc);
  }
  __syncthreads();
  for (int i=tid;i<64*33;i+=512){     // x-proj
    int t=i/33, j=i%33;
    float v=0.f;
    #pragma unroll
    for (int d=0;d<32;d++) v += s_xc[t][d]*xproj_w[j*32+d];
    if (j==0) s_dt[t]=v;
    else if (j<17) s_B[t][j-1]=v;
    else s_C[t][j-17]=v;
  }
  __syncthreads();
  for (int i=tid;i<64*32;i+=512){     // delta (overwrites s_xi)
    int t=i>>5, d=i&31;
    s_xi[t][d] = softplusf(s_dt[t]*dt_w[d] + dt_b[d]);
  }
  __syncthreads();
  {                                    // scan: thread = (d,n), 32*16 = 512 lanes
    int d=tid>>4, n=tid&15;
    float ac = -__expf(Alog[d*16+n])*1.4426950408889634f;
    float h=0.f;
    for (int t=0;t<64;t++){
      float dl = s_xi[t][d];
      float a = exp2f(dl*ac);
      h = a*h + dl*s_xc[t][d]*s_B[t][n];
      float pr = h*s_C[t][n];
      pr += __shfl_xor_sync(0xffffffffu, pr, 8);
      pr += __shfl_xor_sync(0xffffffffu, pr, 4);
      pr += __shfl_xor_sync(0xffffffffu, pr, 2);
      pr += __shfl_xor_sync(0xffffffffu, pr, 1);
      if (n==0) s_y[t][d]=pr;
    }
  }
  __syncthreads();
  if (tid<64){
    int t=tid;
    float skip = skipp[0];
    float yf[32];
    #pragma unroll
    for (int d=0;d<32;d++) yf[d] = (s_y[t][d] + s_xc[t][d]*Dv[d]) * siluf(s_z[t][d]);
    float o[16]; float mu=0.f;
    #pragma unroll
    for (int ch=0;ch<16;ch++){
      float acc = skip * s_x[t][ch];
      #pragma unroll
      for (int d=0;d<32;d++) acc += yf[d]*out_w[ch*32+d];
      o[ch]=acc; mu+=acc;
    }
    mu *= (1.0f/16.0f);
    float var=0.f;
    #pragma unroll
    for (int ch=0;ch<16;ch++){ float dv=o[ch]-mu; var+=dv*dv; }
    var *= (1.0f/16.0f);
    float rs = rsqrtf(var+1e-5f);
    float ln[16];
    #pragma unroll
    for (int ch=0;ch<16;ch++) ln[ch] = (o[ch]-mu)*rs*ng[ch]+nbv[ch];
    #pragma unroll
    for (int j=0;j<16;j++){
      float acc = pb[j];
      #pragma unroll
      for (int ch=0;ch<16;ch++) acc += ln[ch]*pw[j*16+ch];
      out[1835008 + b*3072 + (32+j)*64 + t] = acc;
    }
  }
}

// ---------------- launch ----------------
extern "C" void kernel_launch(void* const* d_in, const int* in_sizes, int n_in,
                              void* d_out, int out_size){
  (void)in_sizes; (void)n_in; (void)out_size;
  const float* t1 = (const float*)d_in[0];
  const float* t2 = (const float*)d_in[1];
  const float* t3 = (const float*)d_in[2];
  const float* t4 = (const float*)d_in[3];
  const float* t5 = (const float*)d_in[4];
  float* out = (float*)d_out;

  k1_gather<<<BTOK/256, 256>>>(t1,t2,t3,t4,t5,(const float*)d_in[5]);
  k3_scanA<<<NB*TOTC, 256>>>((const float*)d_in[8],(const float*)d_in[6],
                             (const float*)d_in[7],(const float*)d_in[9],
                             (const float*)d_in[10],(const float*)d_in[11]);
  k4_chunk<<<32, 256>>>();
  k5_scanC<<<NB*TOTC, 256>>>(t1,t2,t3,t4,t5,
                             (const float*)d_in[8],(const float*)d_in[6],
                             (const float*)d_in[7],(const float*)d_in[9],
                             (const float*)d_in[10],(const float*)d_in[11],
                             (const float*)d_in[13],(const float*)d_in[12],
                             (const float*)d_in[23],(const float*)d_in[24],
                             (const float*)d_in[25],(const float*)d_in[26],
                             (const float*)d_in[31], out);
  k6_m1   <<<NB, 512>>>(t5,(const float*)d_in[14],(const float*)d_in[15],
                        (const float*)d_in[16],(const float*)d_in[17],
                        (const float*)d_in[18],(const float*)d_in[19],
                        (const float*)d_in[20],(const float*)d_in[21],
                        (const float*)d_in[22],(const float*)d_in[27],
                        (const float*)d_in[28],(const float*)d_in[29],
                        (const float*)d_in[30],(const float*)d_in[31], out);
}